// round 1
// baseline (speedup 1.0000x reference)
#include <cuda_runtime.h>

#define NN 50000
#define NE 800000
#define DI 128
#define HH 256

// -------- scratch (static device globals; no runtime allocation) --------
__device__ float g_agg1[(size_t)NN * DI];   // SAGE neighbor sum       (25.6 MB)
__device__ float g_h1s [(size_t)NN * HH];   // h1 * outdeg^-1/2        (51.2 MB)
__device__ float g_agg2[(size_t)NN * HH];   // layer-2 neighbor sum    (51.2 MB)
__device__ int   g_indeg[NN];
__device__ int   g_outdeg[NN];
__device__ float g_wsum[NN];                // sum over out-edges of indeg(dst)^-1/2
__device__ float g_m[HH];                   // sum_u w(u) * h2[u]

__device__ __forceinline__ void red4(float* p, float4 v) {
    asm volatile("red.global.add.v4.f32 [%0], {%1,%2,%3,%4};"
                 :: "l"(__cvta_generic_to_global(p)),
                    "f"(v.x), "f"(v.y), "f"(v.z), "f"(v.w)
                 : "memory");
}

__device__ __forceinline__ float leaky(float x) {
    return (x >= 0.f) ? x : 0.01f * x;
}

// -------- zero scratch each invocation (graph replays must re-zero) --------
__global__ void k_zero() {
    int i = blockIdx.x * blockDim.x + threadIdx.x;
    if (i < NN * HH) g_agg2[i] = 0.f;
    if (i < NN * DI) g_agg1[i] = 0.f;
    if (i < NN) { g_indeg[i] = 0; g_outdeg[i] = 0; g_wsum[i] = 0.f; }
    if (i < HH) g_m[i] = 0.f;
}

__global__ void k_deg(const int* __restrict__ src, const int* __restrict__ dst) {
    int e = blockIdx.x * blockDim.x + threadIdx.x;
    if (e < NE) {
        atomicAdd(&g_indeg[dst[e]], 1);
        atomicAdd(&g_outdeg[src[e]], 1);
    }
}

__global__ void k_wsum(const int* __restrict__ src, const int* __restrict__ dst) {
    int e = blockIdx.x * blockDim.x + threadIdx.x;
    if (e < NE) {
        float r = rsqrtf((float)max(g_indeg[dst[e]], 1));
        atomicAdd(&g_wsum[src[e]], r);
    }
}

// -------- SAGE neighbor aggregation: 32 threads/edge, float4 reductions --------
__global__ void k_agg1(const float* __restrict__ nf,
                       const int* __restrict__ src, const int* __restrict__ dst) {
    int t = blockIdx.x * blockDim.x + threadIdx.x;
    int e = t >> 5;
    if (e >= NE) return;
    int lane = t & 31;
    int s = __ldg(&src[e]);
    int d = __ldg(&dst[e]);
    float4 v = ((const float4*)nf)[(size_t)s * 32 + lane];
    red4(&g_agg1[(size_t)d * DI + lane * 4], v);
}

// -------- layer-2 aggregation of h1s: 64 threads/edge --------
__global__ void k_agg2(const int* __restrict__ src, const int* __restrict__ dst) {
    int t = blockIdx.x * blockDim.x + threadIdx.x;
    int e = t >> 6;
    if (e >= NE) return;
    int lane = t & 63;
    int s = __ldg(&src[e]);
    int d = __ldg(&dst[e]);
    float4 v = ((const float4*)g_h1s)[(size_t)s * 64 + lane];
    red4(&g_agg2[(size_t)d * HH + lane * 4], v);
}

// -------- layer 1 fused GEMM: h1s = leaky([nf | agg1/indeg] @ [Ws;Wn] + b) * outdeg^-1/2
// block: 256 threads, 32 rows x 256 cols, each thread 4 rows x 8 cols.
__global__ __launch_bounds__(256) void k_gemm1(
    const float* __restrict__ nf, const float* __restrict__ Wself,
    const float* __restrict__ Wneigh, const float* __restrict__ bsage)
{
    __shared__ float As[32][32];
    __shared__ float Ws[32][256];
    const int t = threadIdx.x;
    const int lane = t & 31;     // column group: cols lane*4 and 128+lane*4
    const int wrp  = t >> 5;     // row group 0..7
    const int r0   = wrp * 4;
    const int rowLoad = t >> 3;  // 0..31 (A-tile load duty)
    const int qLoad   = t & 7;
    const int blockRow = blockIdx.x * 32;
    const int gRowLoad = blockRow + rowLoad;
    const bool rv = gRowLoad < NN;
    float invmean = 0.f;
    if (rv) invmean = 1.f / (float)max(g_indeg[gRowLoad], 1);

    float acc[4][8];
#pragma unroll
    for (int i = 0; i < 4; i++)
#pragma unroll
        for (int j = 0; j < 8; j++) acc[i][j] = 0.f;

    for (int kk = 0; kk < 2 * DI; kk += 32) {
        __syncthreads();
        float4 av = make_float4(0.f, 0.f, 0.f, 0.f);
        if (rv) {
            if (kk < DI) {
                av = *(const float4*)(nf + (size_t)gRowLoad * DI + kk + qLoad * 4);
            } else {
                av = *(const float4*)(g_agg1 + (size_t)gRowLoad * DI + (kk - DI) + qLoad * 4);
                av.x *= invmean; av.y *= invmean; av.z *= invmean; av.w *= invmean;
            }
        }
        *(float4*)&As[rowLoad][qLoad * 4] = av;

        const float* Wsrc = (kk < DI) ? (Wself + (size_t)kk * HH)
                                      : (Wneigh + (size_t)(kk - DI) * HH);
#pragma unroll
        for (int i = 0; i < 8; i++) {
            int idx = i * 256 + t;         // float4 index within 32x256 slab
            int wr = idx >> 6;
            int wc = idx & 63;
            *(float4*)&Ws[wr][wc * 4] = ((const float4*)Wsrc)[wr * 64 + wc];
        }
        __syncthreads();
#pragma unroll
        for (int k = 0; k < 32; k++) {
            float a0 = As[r0 + 0][k];
            float a1 = As[r0 + 1][k];
            float a2 = As[r0 + 2][k];
            float a3 = As[r0 + 3][k];
            float4 w0 = *(float4*)&Ws[k][lane * 4];
            float4 w1 = *(float4*)&Ws[k][128 + lane * 4];
            acc[0][0] += a0 * w0.x; acc[0][1] += a0 * w0.y; acc[0][2] += a0 * w0.z; acc[0][3] += a0 * w0.w;
            acc[0][4] += a0 * w1.x; acc[0][5] += a0 * w1.y; acc[0][6] += a0 * w1.z; acc[0][7] += a0 * w1.w;
            acc[1][0] += a1 * w0.x; acc[1][1] += a1 * w0.y; acc[1][2] += a1 * w0.z; acc[1][3] += a1 * w0.w;
            acc[1][4] += a1 * w1.x; acc[1][5] += a1 * w1.y; acc[1][6] += a1 * w1.z; acc[1][7] += a1 * w1.w;
            acc[2][0] += a2 * w0.x; acc[2][1] += a2 * w0.y; acc[2][2] += a2 * w0.z; acc[2][3] += a2 * w0.w;
            acc[2][4] += a2 * w1.x; acc[2][5] += a2 * w1.y; acc[2][6] += a2 * w1.z; acc[2][7] += a2 * w1.w;
            acc[3][0] += a3 * w0.x; acc[3][1] += a3 * w0.y; acc[3][2] += a3 * w0.z; acc[3][3] += a3 * w0.w;
            acc[3][4] += a3 * w1.x; acc[3][5] += a3 * w1.y; acc[3][6] += a3 * w1.z; acc[3][7] += a3 * w1.w;
        }
    }

    float4 bv0 = *(const float4*)(bsage + lane * 4);
    float4 bv1 = *(const float4*)(bsage + 128 + lane * 4);
#pragma unroll
    for (int i = 0; i < 4; i++) {
        int r = blockRow + r0 + i;
        if (r < NN) {
            float sc = rsqrtf((float)max(g_outdeg[r], 1));
            float o0 = leaky(acc[i][0] + bv0.x) * sc;
            float o1 = leaky(acc[i][1] + bv0.y) * sc;
            float o2 = leaky(acc[i][2] + bv0.z) * sc;
            float o3 = leaky(acc[i][3] + bv0.w) * sc;
            float o4 = leaky(acc[i][4] + bv1.x) * sc;
            float o5 = leaky(acc[i][5] + bv1.y) * sc;
            float o6 = leaky(acc[i][6] + bv1.z) * sc;
            float o7 = leaky(acc[i][7] + bv1.w) * sc;
            *(float4*)(g_h1s + (size_t)r * HH + lane * 4)       = make_float4(o0, o1, o2, o3);
            *(float4*)(g_h1s + (size_t)r * HH + 128 + lane * 4) = make_float4(o4, o5, o6, o7);
        }
    }
}

// -------- layer 2 fused GEMM + weighted node reduction into g_m --------
// h2[r] = leaky((agg2[r]*indeg^-1/2) @ W1 + b1); g_m += w(r)*h2[r]
__global__ __launch_bounds__(256) void k_gemm2(
    const float* __restrict__ W1, const float* __restrict__ b1)
{
    __shared__ float As[32][32];
    __shared__ float Ws[32][256];
    __shared__ float redsm[8][256];
    const int t = threadIdx.x;
    const int lane = t & 31;
    const int wrp  = t >> 5;
    const int r0   = wrp * 4;
    const int rowLoad = t >> 3;
    const int qLoad   = t & 7;
    const int blockRow = blockIdx.x * 32;
    const int gRowLoad = blockRow + rowLoad;
    const bool rv = gRowLoad < NN;
    float scin = 0.f;
    if (rv) scin = rsqrtf((float)max(g_indeg[gRowLoad], 1));

    float acc[4][8];
#pragma unroll
    for (int i = 0; i < 4; i++)
#pragma unroll
        for (int j = 0; j < 8; j++) acc[i][j] = 0.f;

    for (int kk = 0; kk < HH; kk += 32) {
        __syncthreads();
        float4 av = make_float4(0.f, 0.f, 0.f, 0.f);
        if (rv) {
            av = *(const float4*)(g_agg2 + (size_t)gRowLoad * HH + kk + qLoad * 4);
            av.x *= scin; av.y *= scin; av.z *= scin; av.w *= scin;
        }
        *(float4*)&As[rowLoad][qLoad * 4] = av;

        const float* Wsrc = W1 + (size_t)kk * HH;
#pragma unroll
        for (int i = 0; i < 8; i++) {
            int idx = i * 256 + t;
            int wr = idx >> 6;
            int wc = idx & 63;
            *(float4*)&Ws[wr][wc * 4] = ((const float4*)Wsrc)[wr * 64 + wc];
        }
        __syncthreads();
#pragma unroll
        for (int k = 0; k < 32; k++) {
            float a0 = As[r0 + 0][k];
            float a1 = As[r0 + 1][k];
            float a2 = As[r0 + 2][k];
            float a3 = As[r0 + 3][k];
            float4 w0 = *(float4*)&Ws[k][lane * 4];
            float4 w1 = *(float4*)&Ws[k][128 + lane * 4];
            acc[0][0] += a0 * w0.x; acc[0][1] += a0 * w0.y; acc[0][2] += a0 * w0.z; acc[0][3] += a0 * w0.w;
            acc[0][4] += a0 * w1.x; acc[0][5] += a0 * w1.y; acc[0][6] += a0 * w1.z; acc[0][7] += a0 * w1.w;
            acc[1][0] += a1 * w0.x; acc[1][1] += a1 * w0.y; acc[1][2] += a1 * w0.z; acc[1][3] += a1 * w0.w;
            acc[1][4] += a1 * w1.x; acc[1][5] += a1 * w1.y; acc[1][6] += a1 * w1.z; acc[1][7] += a1 * w1.w;
            acc[2][0] += a2 * w0.x; acc[2][1] += a2 * w0.y; acc[2][2] += a2 * w0.z; acc[2][3] += a2 * w0.w;
            acc[2][4] += a2 * w1.x; acc[2][5] += a2 * w1.y; acc[2][6] += a2 * w1.z; acc[2][7] += a2 * w1.w;
            acc[3][0] += a3 * w0.x; acc[3][1] += a3 * w0.y; acc[3][2] += a3 * w0.z; acc[3][3] += a3 * w0.w;
            acc[3][4] += a3 * w1.x; acc[3][5] += a3 * w1.y; acc[3][6] += a3 * w1.z; acc[3][7] += a3 * w1.w;
        }
    }

    float4 bv0 = *(const float4*)(b1 + lane * 4);
    float4 bv1 = *(const float4*)(b1 + 128 + lane * 4);
    float cs[8];
#pragma unroll
    for (int j = 0; j < 8; j++) cs[j] = 0.f;
#pragma unroll
    for (int i = 0; i < 4; i++) {
        int r = blockRow + r0 + i;
        if (r < NN) {
            float w = g_wsum[r] * rsqrtf((float)max(g_outdeg[r], 1));
            cs[0] += w * leaky(acc[i][0] + bv0.x);
            cs[1] += w * leaky(acc[i][1] + bv0.y);
            cs[2] += w * leaky(acc[i][2] + bv0.z);
            cs[3] += w * leaky(acc[i][3] + bv0.w);
            cs[4] += w * leaky(acc[i][4] + bv1.x);
            cs[5] += w * leaky(acc[i][5] + bv1.y);
            cs[6] += w * leaky(acc[i][6] + bv1.z);
            cs[7] += w * leaky(acc[i][7] + bv1.w);
        }
    }
#pragma unroll
    for (int j = 0; j < 4; j++) redsm[wrp][lane * 4 + j] = cs[j];
#pragma unroll
    for (int j = 0; j < 4; j++) redsm[wrp][128 + lane * 4 + j] = cs[4 + j];
    __syncthreads();
    float s = 0.f;
#pragma unroll
    for (int w = 0; w < 8; w++) s += redsm[w][t];
    atomicAdd(&g_m[t], s);
}

// -------- tiny head: out = (g_m/N) @ {Wo,Wd} + {bo,bd} --------
__global__ void k_head(const float* __restrict__ Wo, const float* __restrict__ bo,
                       const float* __restrict__ Wd, const float* __restrict__ bd,
                       float* __restrict__ out, int out_size)
{
    int j = threadIdx.x;
    if (j >= out_size) return;
    const float invN = 1.0f / (float)NN;
    if (j < 100) {
        float acc = 0.f;
        for (int k = 0; k < HH; k++) acc += g_m[k] * Wo[k * 100 + j];
        out[j] = acc * invN + bo[j];
    } else if (j < 108) {
        int jj = j - 100;
        float acc = 0.f;
        for (int k = 0; k < HH; k++) acc += g_m[k] * Wd[k * 8 + jj];
        out[j] = acc * invN + bd[jj];
    }
}

extern "C" void kernel_launch(void* const* d_in, const int* in_sizes, int n_in,
                              void* d_out, int out_size)
{
    const float* n_feat  = (const float*)d_in[0];
    const int*   src     = (const int*)  d_in[1];
    const int*   dst     = (const int*)  d_in[2];
    const float* W_self  = (const float*)d_in[3];
    const float* W_neigh = (const float*)d_in[4];
    const float* b_sage  = (const float*)d_in[5];
    const float* W1      = (const float*)d_in[6];
    const float* b1      = (const float*)d_in[7];
    const float* Wo      = (const float*)d_in[8];
    const float* bo      = (const float*)d_in[9];
    const float* Wd      = (const float*)d_in[10];
    const float* bd      = (const float*)d_in[11];
    float* out = (float*)d_out;

    k_zero<<<(NN * HH + 255) / 256, 256>>>();
    k_deg<<<(NE + 255) / 256, 256>>>(src, dst);
    k_wsum<<<(NE + 255) / 256, 256>>>(src, dst);
    k_agg1<<<(NE * 32 + 255) / 256, 256>>>(n_feat, src, dst);
    k_gemm1<<<(NN + 31) / 32, 256>>>(n_feat, W_self, W_neigh, b_sage);
    k_agg2<<<(NE / 4), 256>>>(src, dst);   // NE*64/256 threads-per-block
    k_gemm2<<<(NN + 31) / 32, 256>>>(W1, b1);
    k_head<<<1, 128>>>(Wo, bo, Wd, bd, out, out_size);
}

// round 2
// speedup vs baseline: 1.1933x; 1.1933x over previous
#include <cuda_runtime.h>

#define NN 50000
#define NE 800000
#define DI 128
#define HH 256

// -------- scratch (static device globals) --------
__device__ float g_agg1[(size_t)NN * DI];   // mean-aggregated n_feat (25.6 MB)
__device__ float g_h1s [(size_t)NN * HH];   // h1 * outdeg^-1/2       (51.2 MB)
__device__ float g_agg2[(size_t)NN * HH];   // indeg^-1/2 * sum h1s   (51.2 MB)
__device__ int   g_indeg[NN];
__device__ int   g_outdeg[NN];
__device__ float g_wsum[NN];                // sum over out-edges of indeg(dst)^-1/2
__device__ float g_m[HH];                   // sum_u w(u) * h2[u]
__device__ int   g_rowptr[NN + 1];
__device__ int   g_cursor[NN];
__device__ int   g_csrc[NE];

__device__ __forceinline__ float leaky(float x) {
    return (x >= 0.f) ? x : 0.01f * x;
}

// -------- zero the small per-launch state --------
__global__ void k_zero_small() {
    int i = blockIdx.x * blockDim.x + threadIdx.x;
    if (i < NN) { g_indeg[i] = 0; g_outdeg[i] = 0; g_wsum[i] = 0.f; }
    if (i < HH) g_m[i] = 0.f;
}

__global__ void k_deg(const int* __restrict__ src, const int* __restrict__ dst) {
    int e = blockIdx.x * blockDim.x + threadIdx.x;
    if (e < NE) {
        atomicAdd(&g_indeg[dst[e]], 1);
        atomicAdd(&g_outdeg[src[e]], 1);
    }
}

// -------- single-block exclusive scan of indeg -> rowptr, cursor --------
__global__ __launch_bounds__(1024) void k_scan() {
    __shared__ int partial[1024];
    const int C = (NN + 1023) / 1024;     // 49
    int t = threadIdx.x;
    int lo = t * C, hi = min(lo + C, NN);
    int s = 0;
    for (int i = lo; i < hi; i++) s += g_indeg[i];
    partial[t] = s;
    __syncthreads();
    // Hillis-Steele inclusive scan
    for (int off = 1; off < 1024; off <<= 1) {
        int v = (t >= off) ? partial[t - off] : 0;
        __syncthreads();
        partial[t] += v;
        __syncthreads();
    }
    int run = partial[t] - s;             // exclusive base for this chunk
    for (int i = lo; i < hi; i++) {
        int d = g_indeg[i];
        g_rowptr[i] = run;
        g_cursor[i] = run;
        run += d;
    }
    if (t == 1023) g_rowptr[NN] = NE;
}

// -------- scatter edges into CSR (by dst) + accumulate wsum --------
__global__ void k_scatter(const int* __restrict__ src, const int* __restrict__ dst) {
    int e = blockIdx.x * blockDim.x + threadIdx.x;
    if (e >= NE) return;
    int s = src[e];
    int d = dst[e];
    int pos = atomicAdd(&g_cursor[d], 1);
    g_csrc[pos] = s;
    atomicAdd(&g_wsum[s], rsqrtf((float)g_indeg[d]));
}

// -------- SAGE neighbor MEAN aggregation: one warp per node, CSR gather --------
__global__ __launch_bounds__(256) void k_agg1(const float* __restrict__ nf) {
    int w = (blockIdx.x * blockDim.x + threadIdx.x) >> 5;
    if (w >= NN) return;
    int lane = threadIdx.x & 31;
    int beg = g_rowptr[w], end = g_rowptr[w + 1];
    const float4* nf4 = (const float4*)nf;
    float4 acc = make_float4(0.f, 0.f, 0.f, 0.f);
    int i = beg;
    for (; i + 1 < end; i += 2) {
        int s0 = g_csrc[i];
        int s1 = g_csrc[i + 1];
        float4 v0 = nf4[(size_t)s0 * 32 + lane];
        float4 v1 = nf4[(size_t)s1 * 32 + lane];
        acc.x += v0.x + v1.x; acc.y += v0.y + v1.y;
        acc.z += v0.z + v1.z; acc.w += v0.w + v1.w;
    }
    if (i < end) {
        int s0 = g_csrc[i];
        float4 v0 = nf4[(size_t)s0 * 32 + lane];
        acc.x += v0.x; acc.y += v0.y; acc.z += v0.z; acc.w += v0.w;
    }
    float inv = (end > beg) ? 1.f / (float)(end - beg) : 0.f;
    acc.x *= inv; acc.y *= inv; acc.z *= inv; acc.w *= inv;
    ((float4*)g_agg1)[(size_t)w * 32 + lane] = acc;
}

// -------- layer-2 aggregation: one warp per node, 256-wide rows, CSR gather --------
// writes agg2 already scaled by indeg^-1/2
__global__ __launch_bounds__(256) void k_agg2() {
    int w = (blockIdx.x * blockDim.x + threadIdx.x) >> 5;
    if (w >= NN) return;
    int lane = threadIdx.x & 31;
    int beg = g_rowptr[w], end = g_rowptr[w + 1];
    const float4* h4 = (const float4*)g_h1s;
    float4 a0 = make_float4(0.f, 0.f, 0.f, 0.f);
    float4 a1 = make_float4(0.f, 0.f, 0.f, 0.f);
    int i = beg;
    for (; i + 1 < end; i += 2) {
        int s0 = g_csrc[i];
        int s1 = g_csrc[i + 1];
        float4 u0 = h4[(size_t)s0 * 64 + lane];
        float4 u1 = h4[(size_t)s0 * 64 + 32 + lane];
        float4 v0 = h4[(size_t)s1 * 64 + lane];
        float4 v1 = h4[(size_t)s1 * 64 + 32 + lane];
        a0.x += u0.x + v0.x; a0.y += u0.y + v0.y; a0.z += u0.z + v0.z; a0.w += u0.w + v0.w;
        a1.x += u1.x + v1.x; a1.y += u1.y + v1.y; a1.z += u1.z + v1.z; a1.w += u1.w + v1.w;
    }
    if (i < end) {
        int s0 = g_csrc[i];
        float4 u0 = h4[(size_t)s0 * 64 + lane];
        float4 u1 = h4[(size_t)s0 * 64 + 32 + lane];
        a0.x += u0.x; a0.y += u0.y; a0.z += u0.z; a0.w += u0.w;
        a1.x += u1.x; a1.y += u1.y; a1.z += u1.z; a1.w += u1.w;
    }
    float sc = rsqrtf((float)max(end - beg, 1));
    a0.x *= sc; a0.y *= sc; a0.z *= sc; a0.w *= sc;
    a1.x *= sc; a1.y *= sc; a1.z *= sc; a1.w *= sc;
    ((float4*)g_agg2)[(size_t)w * 64 + lane]       = a0;
    ((float4*)g_agg2)[(size_t)w * 64 + 32 + lane]  = a1;
}

// -------- layer 1 fused GEMM: h1s = leaky([nf | agg1] @ [Ws;Wn] + b) * outdeg^-1/2
// 64x256 tile, 256 threads, thread tile 8x8.
__global__ __launch_bounds__(256) void k_gemm1(
    const float* __restrict__ nf, const float* __restrict__ Wself,
    const float* __restrict__ Wneigh, const float* __restrict__ bsage)
{
    __shared__ float As[64][32];
    __shared__ float Ws[32][256];
    const int t = threadIdx.x;
    const int lane = t & 31;
    const int wrp  = t >> 5;
    const int r0   = wrp * 8;
    const int aRow = t >> 3;      // 0..31
    const int q    = t & 7;
    const int blockRow = blockIdx.x * 64;

    float acc[8][8];
#pragma unroll
    for (int i = 0; i < 8; i++)
#pragma unroll
        for (int j = 0; j < 8; j++) acc[i][j] = 0.f;

    const float4* nf4 = (const float4*)nf;
    const float4* ag4 = (const float4*)g_agg1;

    for (int kk = 0; kk < 2 * DI; kk += 32) {
        __syncthreads();
#pragma unroll
        for (int j = 0; j < 2; j++) {
            int row = aRow + j * 32;
            int gr = blockRow + row;
            float4 av = make_float4(0.f, 0.f, 0.f, 0.f);
            if (gr < NN) {
                if (kk < DI) av = nf4[(size_t)gr * 32 + (kk >> 2) + q];
                else         av = ag4[(size_t)gr * 32 + ((kk - DI) >> 2) + q];
            }
            *(float4*)&As[row][q * 4] = av;
        }
        const float* Wsrc = (kk < DI) ? (Wself + (size_t)kk * HH)
                                      : (Wneigh + (size_t)(kk - DI) * HH);
        const float4* Ws4 = (const float4*)Wsrc;
#pragma unroll
        for (int i = 0; i < 8; i++) {
            int idx = i * 256 + t;
            int wr = idx >> 6;
            int wc = idx & 63;
            *(float4*)&Ws[wr][wc * 4] = Ws4[wr * 64 + wc];
        }
        __syncthreads();
#pragma unroll
        for (int k = 0; k < 32; k++) {
            float4 w0 = *(float4*)&Ws[k][lane * 4];
            float4 w1 = *(float4*)&Ws[k][128 + lane * 4];
#pragma unroll
            for (int i = 0; i < 8; i++) {
                float a = As[r0 + i][k];
                acc[i][0] += a * w0.x; acc[i][1] += a * w0.y;
                acc[i][2] += a * w0.z; acc[i][3] += a * w0.w;
                acc[i][4] += a * w1.x; acc[i][5] += a * w1.y;
                acc[i][6] += a * w1.z; acc[i][7] += a * w1.w;
            }
        }
    }

    float4 bv0 = *(const float4*)(bsage + lane * 4);
    float4 bv1 = *(const float4*)(bsage + 128 + lane * 4);
#pragma unroll
    for (int i = 0; i < 8; i++) {
        int r = blockRow + r0 + i;
        if (r < NN) {
            float sc = rsqrtf((float)max(g_outdeg[r], 1));
            float4 o0, o1;
            o0.x = leaky(acc[i][0] + bv0.x) * sc;
            o0.y = leaky(acc[i][1] + bv0.y) * sc;
            o0.z = leaky(acc[i][2] + bv0.z) * sc;
            o0.w = leaky(acc[i][3] + bv0.w) * sc;
            o1.x = leaky(acc[i][4] + bv1.x) * sc;
            o1.y = leaky(acc[i][5] + bv1.y) * sc;
            o1.z = leaky(acc[i][6] + bv1.z) * sc;
            o1.w = leaky(acc[i][7] + bv1.w) * sc;
            *(float4*)(g_h1s + (size_t)r * HH + lane * 4)       = o0;
            *(float4*)(g_h1s + (size_t)r * HH + 128 + lane * 4) = o1;
        }
    }
}

// -------- layer 2 fused GEMM + weighted node reduction into g_m --------
__global__ __launch_bounds__(256) void k_gemm2(
    const float* __restrict__ W1, const float* __restrict__ b1)
{
    __shared__ float As[64][32];
    __shared__ float Ws[32][256];
    __shared__ float redsm[8][256];
    const int t = threadIdx.x;
    const int lane = t & 31;
    const int wrp  = t >> 5;
    const int r0   = wrp * 8;
    const int aRow = t >> 3;
    const int q    = t & 7;
    const int blockRow = blockIdx.x * 64;

    float acc[8][8];
#pragma unroll
    for (int i = 0; i < 8; i++)
#pragma unroll
        for (int j = 0; j < 8; j++) acc[i][j] = 0.f;

    const float4* ag4 = (const float4*)g_agg2;

    for (int kk = 0; kk < HH; kk += 32) {
        __syncthreads();
#pragma unroll
        for (int j = 0; j < 2; j++) {
            int row = aRow + j * 32;
            int gr = blockRow + row;
            float4 av = make_float4(0.f, 0.f, 0.f, 0.f);
            if (gr < NN) av = ag4[(size_t)gr * 64 + (kk >> 2) + q];
            *(float4*)&As[row][q * 4] = av;
        }
        const float4* Ws4 = (const float4*)(W1 + (size_t)kk * HH);
#pragma unroll
        for (int i = 0; i < 8; i++) {
            int idx = i * 256 + t;
            int wr = idx >> 6;
            int wc = idx & 63;
            *(float4*)&Ws[wr][wc * 4] = Ws4[wr * 64 + wc];
        }
        __syncthreads();
#pragma unroll
        for (int k = 0; k < 32; k++) {
            float4 w0 = *(float4*)&Ws[k][lane * 4];
            float4 w1 = *(float4*)&Ws[k][128 + lane * 4];
#pragma unroll
            for (int i = 0; i < 8; i++) {
                float a = As[r0 + i][k];
                acc[i][0] += a * w0.x; acc[i][1] += a * w0.y;
                acc[i][2] += a * w0.z; acc[i][3] += a * w0.w;
                acc[i][4] += a * w1.x; acc[i][5] += a * w1.y;
                acc[i][6] += a * w1.z; acc[i][7] += a * w1.w;
            }
        }
    }

    float4 bv0 = *(const float4*)(b1 + lane * 4);
    float4 bv1 = *(const float4*)(b1 + 128 + lane * 4);
    float cs[8];
#pragma unroll
    for (int j = 0; j < 8; j++) cs[j] = 0.f;
#pragma unroll
    for (int i = 0; i < 8; i++) {
        int r = blockRow + r0 + i;
        if (r < NN) {
            float w = g_wsum[r] * rsqrtf((float)max(g_outdeg[r], 1));
            cs[0] += w * leaky(acc[i][0] + bv0.x);
            cs[1] += w * leaky(acc[i][1] + bv0.y);
            cs[2] += w * leaky(acc[i][2] + bv0.z);
            cs[3] += w * leaky(acc[i][3] + bv0.w);
            cs[4] += w * leaky(acc[i][4] + bv1.x);
            cs[5] += w * leaky(acc[i][5] + bv1.y);
            cs[6] += w * leaky(acc[i][6] + bv1.z);
            cs[7] += w * leaky(acc[i][7] + bv1.w);
        }
    }
#pragma unroll
    for (int j = 0; j < 4; j++) redsm[wrp][lane * 4 + j] = cs[j];
#pragma unroll
    for (int j = 0; j < 4; j++) redsm[wrp][128 + lane * 4 + j] = cs[4 + j];
    __syncthreads();
    float s = 0.f;
#pragma unroll
    for (int w = 0; w < 8; w++) s += redsm[w][t];
    atomicAdd(&g_m[t], s);
}

// -------- tiny head: out = (g_m/N) @ {Wo,Wd} + {bo,bd} --------
__global__ void k_head(const float* __restrict__ Wo, const float* __restrict__ bo,
                       const float* __restrict__ Wd, const float* __restrict__ bd,
                       float* __restrict__ out, int out_size)
{
    int j = threadIdx.x;
    if (j >= out_size) return;
    const float invN = 1.0f / (float)NN;
    if (j < 100) {
        float acc = 0.f;
        for (int k = 0; k < HH; k++) acc += g_m[k] * Wo[k * 100 + j];
        out[j] = acc * invN + bo[j];
    } else if (j < 108) {
        int jj = j - 100;
        float acc = 0.f;
        for (int k = 0; k < HH; k++) acc += g_m[k] * Wd[k * 8 + jj];
        out[j] = acc * invN + bd[jj];
    }
}

extern "C" void kernel_launch(void* const* d_in, const int* in_sizes, int n_in,
                              void* d_out, int out_size)
{
    const float* n_feat  = (const float*)d_in[0];
    const int*   src     = (const int*)  d_in[1];
    const int*   dst     = (const int*)  d_in[2];
    const float* W_self  = (const float*)d_in[3];
    const float* W_neigh = (const float*)d_in[4];
    const float* b_sage  = (const float*)d_in[5];
    const float* W1      = (const float*)d_in[6];
    const float* b1      = (const float*)d_in[7];
    const float* Wo      = (const float*)d_in[8];
    const float* bo      = (const float*)d_in[9];
    const float* Wd      = (const float*)d_in[10];
    const float* bd      = (const float*)d_in[11];
    float* out = (float*)d_out;

    k_zero_small<<<(NN + 255) / 256, 256>>>();
    k_deg<<<(NE + 255) / 256, 256>>>(src, dst);
    k_scan<<<1, 1024>>>();
    k_scatter<<<(NE + 255) / 256, 256>>>(src, dst);
    k_agg1<<<(NN * 32 + 255) / 256, 256>>>(n_feat);
    k_gemm1<<<(NN + 63) / 64, 256>>>(n_feat, W_self, W_neigh, b_sage);
    k_agg2<<<(NN * 32 + 255) / 256, 256>>>();
    k_gemm2<<<(NN + 63) / 64, 256>>>(W1, b1);
    k_head<<<1, 128>>>(Wo, bo, Wd, bd, out, out_size);
}

// round 4
// speedup vs baseline: 1.9364x; 1.6228x over previous
#include <cuda_runtime.h>
#include <cstdint>

#define NN 50000
#define NE 800000
#define DI 128
#define HH 256

// -------- scratch (static device globals) --------
__device__ float g_agg1[(size_t)NN * DI];   // mean-aggregated n_feat (25.6 MB)
__device__ float g_h1s [(size_t)NN * HH];   // h1 * outdeg^-1/2       (51.2 MB)
__device__ float g_agg2[(size_t)NN * HH];   // indeg^-1/2 * sum h1s   (51.2 MB)
__device__ int   g_indeg[NN];
__device__ int   g_outdeg[NN];
__device__ float g_wsum[NN];                // sum over out-edges of indeg(dst)^-1/2
__device__ float g_m[HH];                   // sum_u w(u) * h2[u]
__device__ int   g_rowptr[NN + 1];
__device__ int   g_cursor[NN];
__device__ int   g_csrc[NE];

__device__ __forceinline__ float leaky(float x) {
    return (x >= 0.f) ? x : 0.01f * x;
}

__device__ __forceinline__ uint32_t f2tf(float x) {
    uint32_t y;
    asm("cvt.rna.tf32.f32 %0, %1;" : "=r"(y) : "f"(x));
    return y;
}

__device__ __forceinline__ void mma_tf32(float c[4],
    uint32_t a0, uint32_t a1, uint32_t a2, uint32_t a3,
    uint32_t b0, uint32_t b1)
{
    asm volatile(
        "mma.sync.aligned.m16n8k8.row.col.f32.tf32.tf32.f32 "
        "{%0,%1,%2,%3},{%4,%5,%6,%7},{%8,%9},{%0,%1,%2,%3};"
        : "+f"(c[0]), "+f"(c[1]), "+f"(c[2]), "+f"(c[3])
        : "r"(a0), "r"(a1), "r"(a2), "r"(a3), "r"(b0), "r"(b1));
}

// -------- zero the small per-launch state --------
__global__ void k_zero_small() {
    int i = blockIdx.x * blockDim.x + threadIdx.x;
    if (i < NN) { g_indeg[i] = 0; g_outdeg[i] = 0; g_wsum[i] = 0.f; }
    if (i < HH) g_m[i] = 0.f;
}

__global__ void k_deg(const int* __restrict__ src, const int* __restrict__ dst) {
    int e = blockIdx.x * blockDim.x + threadIdx.x;
    if (e < NE) {
        atomicAdd(&g_indeg[dst[e]], 1);
        atomicAdd(&g_outdeg[src[e]], 1);
    }
}

// -------- single-block exclusive scan of indeg -> rowptr, cursor --------
__global__ __launch_bounds__(1024) void k_scan() {
    __shared__ int partial[1024];
    const int C = (NN + 1023) / 1024;     // 49
    int t = threadIdx.x;
    int lo = t * C, hi = min(lo + C, NN);
    int s = 0;
    for (int i = lo; i < hi; i++) s += g_indeg[i];
    partial[t] = s;
    __syncthreads();
    for (int off = 1; off < 1024; off <<= 1) {
        int v = (t >= off) ? partial[t - off] : 0;
        __syncthreads();
        partial[t] += v;
        __syncthreads();
    }
    int run = partial[t] - s;
    for (int i = lo; i < hi; i++) {
        int d = g_indeg[i];
        g_rowptr[i] = run;
        g_cursor[i] = run;
        run += d;
    }
    if (t == 1023) g_rowptr[NN] = NE;
}

// -------- scatter edges into CSR (by dst) + accumulate wsum --------
__global__ void k_scatter(const int* __restrict__ src, const int* __restrict__ dst) {
    int e = blockIdx.x * blockDim.x + threadIdx.x;
    if (e >= NE) return;
    int s = src[e];
    int d = dst[e];
    int pos = atomicAdd(&g_cursor[d], 1);
    g_csrc[pos] = s;
    atomicAdd(&g_wsum[s], rsqrtf((float)g_indeg[d]));
}

// -------- SAGE neighbor MEAN aggregation: one warp per node, CSR gather --------
__global__ __launch_bounds__(256) void k_agg1(const float* __restrict__ nf) {
    int w = (blockIdx.x * blockDim.x + threadIdx.x) >> 5;
    if (w >= NN) return;
    int lane = threadIdx.x & 31;
    int beg = g_rowptr[w], end = g_rowptr[w + 1];
    const float4* nf4 = (const float4*)nf;
    float4 acc = make_float4(0.f, 0.f, 0.f, 0.f);
    int i = beg;
    for (; i + 1 < end; i += 2) {
        int s0 = g_csrc[i];
        int s1 = g_csrc[i + 1];
        float4 v0 = nf4[(size_t)s0 * 32 + lane];
        float4 v1 = nf4[(size_t)s1 * 32 + lane];
        acc.x += v0.x + v1.x; acc.y += v0.y + v1.y;
        acc.z += v0.z + v1.z; acc.w += v0.w + v1.w;
    }
    if (i < end) {
        int s0 = g_csrc[i];
        float4 v0 = nf4[(size_t)s0 * 32 + lane];
        acc.x += v0.x; acc.y += v0.y; acc.z += v0.z; acc.w += v0.w;
    }
    float inv = (end > beg) ? 1.f / (float)(end - beg) : 0.f;
    acc.x *= inv; acc.y *= inv; acc.z *= inv; acc.w *= inv;
    ((float4*)g_agg1)[(size_t)w * 32 + lane] = acc;
}

// -------- layer-2 aggregation: one warp per node, CSR gather, scaled by indeg^-1/2 --------
__global__ __launch_bounds__(256) void k_agg2() {
    int w = (blockIdx.x * blockDim.x + threadIdx.x) >> 5;
    if (w >= NN) return;
    int lane = threadIdx.x & 31;
    int beg = g_rowptr[w], end = g_rowptr[w + 1];
    const float4* h4 = (const float4*)g_h1s;
    float4 a0 = make_float4(0.f, 0.f, 0.f, 0.f);
    float4 a1 = make_float4(0.f, 0.f, 0.f, 0.f);
    int i = beg;
    for (; i + 1 < end; i += 2) {
        int s0 = g_csrc[i];
        int s1 = g_csrc[i + 1];
        float4 u0 = h4[(size_t)s0 * 64 + lane];
        float4 u1 = h4[(size_t)s0 * 64 + 32 + lane];
        float4 v0 = h4[(size_t)s1 * 64 + lane];
        float4 v1 = h4[(size_t)s1 * 64 + 32 + lane];
        a0.x += u0.x + v0.x; a0.y += u0.y + v0.y; a0.z += u0.z + v0.z; a0.w += u0.w + v0.w;
        a1.x += u1.x + v1.x; a1.y += u1.y + v1.y; a1.z += u1.z + v1.z; a1.w += u1.w + v1.w;
    }
    if (i < end) {
        int s0 = g_csrc[i];
        float4 u0 = h4[(size_t)s0 * 64 + lane];
        float4 u1 = h4[(size_t)s0 * 64 + 32 + lane];
        a0.x += u0.x; a0.y += u0.y; a0.z += u0.z; a0.w += u0.w;
        a1.x += u1.x; a1.y += u1.y; a1.z += u1.z; a1.w += u1.w;
    }
    float sc = rsqrtf((float)max(end - beg, 1));
    a0.x *= sc; a0.y *= sc; a0.z *= sc; a0.w *= sc;
    a1.x *= sc; a1.y *= sc; a1.z *= sc; a1.w *= sc;
    ((float4*)g_agg2)[(size_t)w * 64 + lane]      = a0;
    ((float4*)g_agg2)[(size_t)w * 64 + 32 + lane] = a1;
}

// ============ tf32 tensor-core GEMM 1 ============
// h1s[r,:] = leaky([nf | agg1][r,:] @ [Wself;Wneigh] + b) * outdeg(r)^-1/2
// block 128x128, BK=32, 256 threads, 8 warps (2 row x 4 col), warp tile 64x32
__global__ __launch_bounds__(256) void k_gemm1(
    const float* __restrict__ nf, const float* __restrict__ Wself,
    const float* __restrict__ Wneigh, const float* __restrict__ bsage)
{
    __shared__ uint32_t As[128][36];   // [m][k], pad 36
    __shared__ uint32_t Bs[32][132];   // [k][n], pad 132
    const int t = threadIdx.x;
    const int lane = t & 31;
    const int warp = t >> 5;
    const int wr = warp >> 2;          // 0..1
    const int wc = warp & 3;           // 0..3
    const int blockRow = blockIdx.x * 128;
    const int n0 = blockIdx.y * 128;

    float c[4][4][4];
#pragma unroll
    for (int i = 0; i < 4; i++)
#pragma unroll
        for (int j = 0; j < 4; j++)
#pragma unroll
            for (int q = 0; q < 4; q++) c[i][j][q] = 0.f;

    const float4* nf4 = (const float4*)nf;
    const float4* ag4 = (const float4*)g_agg1;

    for (int kk = 0; kk < 2 * DI; kk += 32) {
        const float4* Asrc = (kk < DI) ? (nf4 + (kk >> 2)) : (ag4 + ((kk - DI) >> 2));
        const float4* Bsrc = (const float4*)((kk < DI) ? (Wself + (size_t)kk * HH)
                                                       : (Wneigh + (size_t)(kk - DI) * HH));
        __syncthreads();
#pragma unroll
        for (int i = 0; i < 4; i++) {
            int idx = i * 256 + t;
            int row = idx >> 3;        // 0..127
            int q   = idx & 7;
            int gr  = blockRow + row;
            float4 av = make_float4(0.f, 0.f, 0.f, 0.f);
            if (gr < NN) av = Asrc[(size_t)gr * 32 + q];
            uint4 u = make_uint4(f2tf(av.x), f2tf(av.y), f2tf(av.z), f2tf(av.w));
            *(uint4*)&As[row][q * 4] = u;
        }
#pragma unroll
        for (int i = 0; i < 4; i++) {
            int idx = i * 256 + t;
            int kr = idx >> 5;         // 0..31
            int c4 = idx & 31;         // float4 col within 128
            float4 bv = Bsrc[(size_t)kr * 64 + (n0 >> 2) + c4];
            uint4 u = make_uint4(f2tf(bv.x), f2tf(bv.y), f2tf(bv.z), f2tf(bv.w));
            *(uint4*)&Bs[kr][c4 * 4] = u;
        }
        __syncthreads();
#pragma unroll
        for (int ks = 0; ks < 4; ks++) {
            int k = ks * 8;
            uint32_t a[4][4], b[4][2];
#pragma unroll
            for (int i = 0; i < 4; i++) {
                int m = wr * 64 + i * 16 + (lane >> 2);
                a[i][0] = As[m][k + (lane & 3)];
                a[i][1] = As[m + 8][k + (lane & 3)];
                a[i][2] = As[m][k + 4 + (lane & 3)];
                a[i][3] = As[m + 8][k + 4 + (lane & 3)];
            }
#pragma unroll
            for (int j = 0; j < 4; j++) {
                int n = wc * 32 + j * 8 + (lane >> 2);
                b[j][0] = Bs[k + (lane & 3)][n];
                b[j][1] = Bs[k + 4 + (lane & 3)][n];
            }
#pragma unroll
            for (int i = 0; i < 4; i++)
#pragma unroll
                for (int j = 0; j < 4; j++)
                    mma_tf32(c[i][j], a[i][0], a[i][1], a[i][2], a[i][3], b[j][0], b[j][1]);
        }
    }

    // epilogue
#pragma unroll
    for (int i = 0; i < 4; i++) {
        int r0 = blockRow + wr * 64 + i * 16 + (lane >> 2);
        int r1 = r0 + 8;
        float s0 = (r0 < NN) ? rsqrtf((float)max(g_outdeg[r0], 1)) : 0.f;
        float s1 = (r1 < NN) ? rsqrtf((float)max(g_outdeg[r1], 1)) : 0.f;
#pragma unroll
        for (int j = 0; j < 4; j++) {
            int col = n0 + wc * 32 + j * 8 + (lane & 3) * 2;
            float bx = bsage[col], by = bsage[col + 1];
            if (r0 < NN) {
                float2 v = make_float2(leaky(c[i][j][0] + bx) * s0,
                                       leaky(c[i][j][1] + by) * s0);
                *(float2*)(g_h1s + (size_t)r0 * HH + col) = v;
            }
            if (r1 < NN) {
                float2 v = make_float2(leaky(c[i][j][2] + bx) * s1,
                                       leaky(c[i][j][3] + by) * s1);
                *(float2*)(g_h1s + (size_t)r1 * HH + col) = v;
            }
        }
    }
}

// ============ tf32 tensor-core GEMM 2 + fused weighted node reduction ============
// h2[r,:] = leaky(agg2[r,:] @ W1 + b1);  g_m[:] += w(r) * h2[r,:]
__global__ __launch_bounds__(256) void k_gemm2(
    const float* __restrict__ W1, const float* __restrict__ b1)
{
    __shared__ uint32_t As[128][36];
    __shared__ uint32_t Bs[32][132];
    __shared__ float colacc[128];
    const int t = threadIdx.x;
    const int lane = t & 31;
    const int warp = t >> 5;
    const int wr = warp >> 2;
    const int wc = warp & 3;
    const int blockRow = blockIdx.x * 128;
    const int n0 = blockIdx.y * 128;

    if (t < 128) colacc[t] = 0.f;

    float c[4][4][4];
#pragma unroll
    for (int i = 0; i < 4; i++)
#pragma unroll
        for (int j = 0; j < 4; j++)
#pragma unroll
            for (int q = 0; q < 4; q++) c[i][j][q] = 0.f;

    const float4* ag4 = (const float4*)g_agg2;

    for (int kk = 0; kk < HH; kk += 32) {
        const float4* Bsrc = (const float4*)(W1 + (size_t)kk * HH);
        __syncthreads();
#pragma unroll
        for (int i = 0; i < 4; i++) {
            int idx = i * 256 + t;
            int row = idx >> 3;
            int q   = idx & 7;
            int gr  = blockRow + row;
            float4 av = make_float4(0.f, 0.f, 0.f, 0.f);
            if (gr < NN) av = ag4[(size_t)gr * 64 + (kk >> 2) + q];
            uint4 u = make_uint4(f2tf(av.x), f2tf(av.y), f2tf(av.z), f2tf(av.w));
            *(uint4*)&As[row][q * 4] = u;
        }
#pragma unroll
        for (int i = 0; i < 4; i++) {
            int idx = i * 256 + t;
            int kr = idx >> 5;
            int c4 = idx & 31;
            float4 bv = Bsrc[(size_t)kr * 64 + (n0 >> 2) + c4];
            uint4 u = make_uint4(f2tf(bv.x), f2tf(bv.y), f2tf(bv.z), f2tf(bv.w));
            *(uint4*)&Bs[kr][c4 * 4] = u;
        }
        __syncthreads();
#pragma unroll
        for (int ks = 0; ks < 4; ks++) {
            int k = ks * 8;
            uint32_t a[4][4], b[4][2];
#pragma unroll
            for (int i = 0; i < 4; i++) {
                int m = wr * 64 + i * 16 + (lane >> 2);
                a[i][0] = As[m][k + (lane & 3)];
                a[i][1] = As[m + 8][k + (lane & 3)];
                a[i][2] = As[m][k + 4 + (lane & 3)];
                a[i][3] = As[m + 8][k + 4 + (lane & 3)];
            }
#pragma unroll
            for (int j = 0; j < 4; j++) {
                int n = wc * 32 + j * 8 + (lane >> 2);
                b[j][0] = Bs[k + (lane & 3)][n];
                b[j][1] = Bs[k + 4 + (lane & 3)][n];
            }
#pragma unroll
            for (int i = 0; i < 4; i++)
#pragma unroll
                for (int j = 0; j < 4; j++)
                    mma_tf32(c[i][j], a[i][0], a[i][1], a[i][2], a[i][3], b[j][0], b[j][1]);
        }
    }

    // epilogue: weighted column sums
    float w0v[4], w1v[4];
#pragma unroll
    for (int i = 0; i < 4; i++) {
        int r0 = blockRow + wr * 64 + i * 16 + (lane >> 2);
        int r1 = r0 + 8;
        w0v[i] = (r0 < NN) ? g_wsum[r0] * rsqrtf((float)max(g_outdeg[r0], 1)) : 0.f;
        w1v[i] = (r1 < NN) ? g_wsum[r1] * rsqrtf((float)max(g_outdeg[r1], 1)) : 0.f;
    }
#pragma unroll
    for (int j = 0; j < 4; j++) {
        int lc = wc * 32 + j * 8 + (lane & 3) * 2;
        float bx = b1[n0 + lc], by = b1[n0 + lc + 1];
        float accLo = 0.f, accHi = 0.f;
#pragma unroll
        for (int i = 0; i < 4; i++) {
            accLo += w0v[i] * leaky(c[i][j][0] + bx) + w1v[i] * leaky(c[i][j][2] + bx);
            accHi += w0v[i] * leaky(c[i][j][1] + by) + w1v[i] * leaky(c[i][j][3] + by);
        }
        atomicAdd(&colacc[lc], accLo);
        atomicAdd(&colacc[lc + 1], accHi);
    }
    __syncthreads();
    if (t < 128) atomicAdd(&g_m[n0 + t], colacc[t]);
}

// -------- tiny head: out = (g_m/N) @ {Wo,Wd} + {bo,bd} --------
__global__ void k_head(const float* __restrict__ Wo, const float* __restrict__ bo,
                       const float* __restrict__ Wd, const float* __restrict__ bd,
                       float* __restrict__ out, int out_size)
{
    int j = threadIdx.x;
    if (j >= out_size) return;
    const float invN = 1.0f / (float)NN;
    if (j < 100) {
        float acc = 0.f;
        for (int k = 0; k < HH; k++) acc += g_m[k] * Wo[k * 100 + j];
        out[j] = acc * invN + bo[j];
    } else if (j < 108) {
        int jj = j - 100;
        float acc = 0.f;
        for (int k = 0; k < HH; k++) acc += g_m[k] * Wd[k * 8 + jj];
        out[j] = acc * invN + bd[jj];
    }
}

extern "C" void kernel_launch(void* const* d_in, const int* in_sizes, int n_in,
                              void* d_out, int out_size)
{
    const float* n_feat  = (const float*)d_in[0];
    const int*   src     = (const int*)  d_in[1];
    const int*   dst     = (const int*)  d_in[2];
    const float* W_self  = (const float*)d_in[3];
    const float* W_neigh = (const float*)d_in[4];
    const float* b_sage  = (const float*)d_in[5];
    const float* W1      = (const float*)d_in[6];
    const float* b1      = (const float*)d_in[7];
    const float* Wo      = (const float*)d_in[8];
    const float* bo      = (const float*)d_in[9];
    const float* Wd      = (const float*)d_in[10];
    const float* bd      = (const float*)d_in[11];
    float* out = (float*)d_out;

    dim3 ggrid((NN + 127) / 128, 2);

    k_zero_small<<<(NN + 255) / 256, 256>>>();
    k_deg<<<(NE + 255) / 256, 256>>>(src, dst);
    k_scan<<<1, 1024>>>();
    k_scatter<<<(NE + 255) / 256, 256>>>(src, dst);
    k_agg1<<<(NN * 32 + 255) / 256, 256>>>(n_feat);
    k_gemm1<<<ggrid, 256>>>(n_feat, W_self, W_neigh, b_sage);
    k_agg2<<<(NN * 32 + 255) / 256, 256>>>();
    k_gemm2<<<ggrid, 256>>>(W1, b1);
    k_head<<<1, 128>>>(Wo, bo, Wd, bd, out, out_size);
}

// round 5
// speedup vs baseline: 2.3131x; 1.1946x over previous
#include <cuda_runtime.h>
#include <cuda_fp16.h>
#include <cstdint>

#define NN 50000
#define NE 800000
#define DI 128
#define HH 256

// -------- scratch (static device globals) --------
__device__ __half g_nfh [(size_t)NN * DI];  // fp16 copy of n_feat    (12.8 MB)
__device__ float  g_agg1[(size_t)NN * DI];  // mean-aggregated n_feat (25.6 MB)
__device__ __half g_h1h [(size_t)NN * HH];  // h1 * outdeg^-1/2 fp16  (25.6 MB)
__device__ float  g_agg2[(size_t)NN * HH];  // indeg^-1/2 * sum h1s   (51.2 MB)
__device__ int    g_indeg[NN];
__device__ int    g_outdeg[NN];
__device__ float  g_wsum[NN];               // sum over out-edges of indeg(dst)^-1/2
__device__ float  g_m[HH];                  // sum_u w(u) * h2[u]
__device__ int    g_beg[NN];
__device__ int    g_cursor[NN];
__device__ int    g_csrc[NE];
__device__ int    g_total;

__device__ __forceinline__ float leaky(float x) {
    return (x >= 0.f) ? x : 0.01f * x;
}

__device__ __forceinline__ uint32_t f2tf(float x) {
    uint32_t y;
    asm("cvt.rna.tf32.f32 %0, %1;" : "=r"(y) : "f"(x));
    return y;
}

__device__ __forceinline__ void mma_tf32(float c[4],
    uint32_t a0, uint32_t a1, uint32_t a2, uint32_t a3,
    uint32_t b0, uint32_t b1)
{
    asm volatile(
        "mma.sync.aligned.m16n8k8.row.col.f32.tf32.tf32.f32 "
        "{%0,%1,%2,%3},{%4,%5,%6,%7},{%8,%9},{%0,%1,%2,%3};"
        : "+f"(c[0]), "+f"(c[1]), "+f"(c[2]), "+f"(c[3])
        : "r"(a0), "r"(a1), "r"(a2), "r"(a3), "r"(b0), "r"(b1));
}

// -------- zero the small per-launch state --------
__global__ void k_zero_small() {
    int i = blockIdx.x * blockDim.x + threadIdx.x;
    if (i < NN) { g_indeg[i] = 0; g_outdeg[i] = 0; g_wsum[i] = 0.f; }
    if (i < HH) g_m[i] = 0.f;
    if (i == 0) g_total = 0;
}

__global__ void k_deg(const int* __restrict__ src, const int* __restrict__ dst) {
    int e = blockIdx.x * blockDim.x + threadIdx.x;
    if (e < NE) {
        atomicAdd(&g_indeg[dst[e]], 1);
        atomicAdd(&g_outdeg[src[e]], 1);
    }
}

// -------- assign CSR row bases: warp-scan + one atomic per warp (order-free) --------
__global__ __launch_bounds__(256) void k_assign() {
    int i = blockIdx.x * blockDim.x + threadIdx.x;
    int lane = threadIdx.x & 31;
    int d = (i < NN) ? g_indeg[i] : 0;
    int x = d;
#pragma unroll
    for (int off = 1; off < 32; off <<= 1) {
        int y = __shfl_up_sync(0xffffffffu, x, off);
        if (lane >= off) x += y;
    }
    int base = 0;
    if (lane == 31) base = atomicAdd(&g_total, x);
    base = __shfl_sync(0xffffffffu, base, 31);
    if (i < NN) {
        int b = base + x - d;
        g_beg[i] = b;
        g_cursor[i] = b;
    }
}

// -------- scatter edges into CSR (by dst) + accumulate wsum --------
__global__ void k_scatter(const int* __restrict__ src, const int* __restrict__ dst) {
    int e = blockIdx.x * blockDim.x + threadIdx.x;
    if (e >= NE) return;
    int s = src[e];
    int d = dst[e];
    int pos = atomicAdd(&g_cursor[d], 1);
    g_csrc[pos] = s;
    atomicAdd(&g_wsum[s], rsqrtf((float)g_indeg[d]));
}

// -------- n_feat -> fp16 copy --------
__global__ void k_nf2h(const float* __restrict__ nf) {
    int i = blockIdx.x * blockDim.x + threadIdx.x;
    if (i < NN * DI / 2) {
        float2 v = ((const float2*)nf)[i];
        ((__half2*)g_nfh)[i] = __floats2half2_rn(v.x, v.y);
    }
}

// -------- SAGE neighbor MEAN aggregation: warp/node, fp16 gather --------
__global__ __launch_bounds__(256) void k_agg1() {
    int w = (blockIdx.x * blockDim.x + threadIdx.x) >> 5;
    if (w >= NN) return;
    int lane = threadIdx.x & 31;
    int beg = g_beg[w];
    int deg = g_indeg[w];
    int end = beg + deg;
    const uint2* nh = (const uint2*)g_nfh;   // 4 halves per uint2; 32 per row
    float a0 = 0.f, a1 = 0.f, a2 = 0.f, a3 = 0.f;
    int i = beg;
    for (; i + 1 < end; i += 2) {
        int s0 = g_csrc[i];
        int s1 = g_csrc[i + 1];
        uint2 u = nh[(size_t)s0 * 32 + lane];
        uint2 v = nh[(size_t)s1 * 32 + lane];
        float2 f0 = __half22float2(*(__half2*)&u.x);
        float2 f1 = __half22float2(*(__half2*)&u.y);
        float2 g0 = __half22float2(*(__half2*)&v.x);
        float2 g1 = __half22float2(*(__half2*)&v.y);
        a0 += f0.x + g0.x; a1 += f0.y + g0.y;
        a2 += f1.x + g1.x; a3 += f1.y + g1.y;
    }
    if (i < end) {
        int s0 = g_csrc[i];
        uint2 u = nh[(size_t)s0 * 32 + lane];
        float2 f0 = __half22float2(*(__half2*)&u.x);
        float2 f1 = __half22float2(*(__half2*)&u.y);
        a0 += f0.x; a1 += f0.y; a2 += f1.x; a3 += f1.y;
    }
    float inv = (deg > 0) ? 1.f / (float)deg : 0.f;
    float4 o = make_float4(a0 * inv, a1 * inv, a2 * inv, a3 * inv);
    *(float4*)(g_agg1 + (size_t)w * DI + lane * 4) = o;
}

// -------- layer-2 aggregation: warp/node, fp16 gather, scaled by indeg^-1/2 --------
__global__ __launch_bounds__(256) void k_agg2() {
    int w = (blockIdx.x * blockDim.x + threadIdx.x) >> 5;
    if (w >= NN) return;
    int lane = threadIdx.x & 31;
    int beg = g_beg[w];
    int deg = g_indeg[w];
    int end = beg + deg;
    const uint4* hh = (const uint4*)g_h1h;   // 8 halves per uint4; 32 per row
    float acc[8];
#pragma unroll
    for (int q = 0; q < 8; q++) acc[q] = 0.f;
    int i = beg;
    for (; i + 1 < end; i += 2) {
        int s0 = g_csrc[i];
        int s1 = g_csrc[i + 1];
        uint4 u = hh[(size_t)s0 * 32 + lane];
        uint4 v = hh[(size_t)s1 * 32 + lane];
        const uint32_t* up = &u.x;
        const uint32_t* vp = &v.x;
#pragma unroll
        for (int q = 0; q < 4; q++) {
            float2 fu = __half22float2(*(__half2*)&up[q]);
            float2 fv = __half22float2(*(__half2*)&vp[q]);
            acc[2 * q]     += fu.x + fv.x;
            acc[2 * q + 1] += fu.y + fv.y;
        }
    }
    if (i < end) {
        int s0 = g_csrc[i];
        uint4 u = hh[(size_t)s0 * 32 + lane];
        const uint32_t* up = &u.x;
#pragma unroll
        for (int q = 0; q < 4; q++) {
            float2 fu = __half22float2(*(__half2*)&up[q]);
            acc[2 * q]     += fu.x;
            acc[2 * q + 1] += fu.y;
        }
    }
    float sc = rsqrtf((float)max(deg, 1));
    float4 o0 = make_float4(acc[0] * sc, acc[1] * sc, acc[2] * sc, acc[3] * sc);
    float4 o1 = make_float4(acc[4] * sc, acc[5] * sc, acc[6] * sc, acc[7] * sc);
    *(float4*)(g_agg2 + (size_t)w * HH + lane * 8)     = o0;
    *(float4*)(g_agg2 + (size_t)w * HH + lane * 8 + 4) = o1;
}

// ============ tf32 GEMM, 128x256 tile, XOR-swizzled smem ============
// As: [128][32] words, value (row,k) at row*32 + ((k>>2)^(row&7))*4 + (k&3)
// Bs: [32][256] words, value (k,n)  at k*256  + (n ^ ((k&3)<<3))
// 8 warps: wr=warp>>2 (M 64), wc=warp&3 (N 64); frags i0..3 (m16), j0..7 (n8), ks0..3

// GEMM1: h1h[r,:] = fp16( leaky([nf | agg1][r,:] @ [Wself;Wneigh] + b) * outdeg^-1/2 )
__global__ __launch_bounds__(256, 1) void k_gemm1(
    const float* __restrict__ nf, const float* __restrict__ Wself,
    const float* __restrict__ Wneigh, const float* __restrict__ bsage)
{
    __shared__ uint32_t As[128 * 32];
    __shared__ uint32_t Bs[32 * 256];
    const int t = threadIdx.x;
    const int lane = t & 31;
    const int warp = t >> 5;
    const int wr = warp >> 2;
    const int wc = warp & 3;
    const int r4 = lane >> 2;
    const int c4 = lane & 3;
    const int blockRow = blockIdx.x * 128;

    float c[4][8][4];
#pragma unroll
    for (int i = 0; i < 4; i++)
#pragma unroll
        for (int j = 0; j < 8; j++)
#pragma unroll
            for (int q = 0; q < 4; q++) c[i][j][q] = 0.f;

    const float4* nf4 = (const float4*)nf;
    const float4* ag4 = (const float4*)g_agg1;

    for (int kk = 0; kk < 2 * DI; kk += 32) {
        const float4* Asrc = (kk < DI) ? (nf4 + (kk >> 2)) : (ag4 + ((kk - DI) >> 2));
        const float4* Bsrc = (const float4*)((kk < DI) ? (Wself + (size_t)kk * HH)
                                                       : (Wneigh + (size_t)(kk - DI) * HH));
        __syncthreads();
#pragma unroll
        for (int i = 0; i < 4; i++) {
            int idx = i * 256 + t;
            int row = idx >> 3;
            int q   = idx & 7;
            int gr  = blockRow + row;
            float4 av = make_float4(0.f, 0.f, 0.f, 0.f);
            if (gr < NN) av = Asrc[(size_t)gr * 32 + q];
            uint4 u = make_uint4(f2tf(av.x), f2tf(av.y), f2tf(av.z), f2tf(av.w));
            *(uint4*)&As[row * 32 + (q ^ (row & 7)) * 4] = u;
        }
#pragma unroll
        for (int i = 0; i < 8; i++) {
            int idx = i * 256 + t;
            int kr  = idx >> 6;
            int c44 = idx & 63;
            float4 bv = Bsrc[(size_t)kr * 64 + c44];
            uint4 u = make_uint4(f2tf(bv.x), f2tf(bv.y), f2tf(bv.z), f2tf(bv.w));
            *(uint4*)&Bs[kr * 256 + (c44 ^ ((kr & 3) << 1)) * 4] = u;
        }
        __syncthreads();
#pragma unroll
        for (int ks = 0; ks < 4; ks++) {
            uint32_t a[4][4], b[8][2];
#pragma unroll
            for (int i = 0; i < 4; i++) {
                int m  = wr * 64 + i * 16 + r4;
                int m7 = m & 7;
                int cA0 = (((ks * 2)     ^ m7) << 2) | c4;
                int cA1 = (((ks * 2 + 1) ^ m7) << 2) | c4;
                a[i][0] = As[m * 32 + cA0];
                a[i][1] = As[(m + 8) * 32 + cA0];
                a[i][2] = As[m * 32 + cA1];
                a[i][3] = As[(m + 8) * 32 + cA1];
            }
            int k0 = ks * 8 + c4;
#pragma unroll
            for (int j = 0; j < 8; j++) {
                int n = wc * 64 + j * 8 + r4;
                int colB = n ^ (c4 << 3);
                b[j][0] = Bs[k0 * 256 + colB];
                b[j][1] = Bs[(k0 + 4) * 256 + colB];
            }
#pragma unroll
            for (int i = 0; i < 4; i++)
#pragma unroll
                for (int j = 0; j < 8; j++)
                    mma_tf32(c[i][j], a[i][0], a[i][1], a[i][2], a[i][3], b[j][0], b[j][1]);
        }
    }

    // epilogue: bias + leaky + outdeg^-1/2, store fp16
#pragma unroll
    for (int i = 0; i < 4; i++) {
        int r0 = blockRow + wr * 64 + i * 16 + r4;
        int r1 = r0 + 8;
        float s0 = (r0 < NN) ? rsqrtf((float)max(g_outdeg[r0], 1)) : 0.f;
        float s1 = (r1 < NN) ? rsqrtf((float)max(g_outdeg[r1], 1)) : 0.f;
#pragma unroll
        for (int j = 0; j < 8; j++) {
            int col = wc * 64 + j * 8 + c4 * 2;
            float bx = bsage[col], by = bsage[col + 1];
            if (r0 < NN) {
                __half2 v = __floats2half2_rn(leaky(c[i][j][0] + bx) * s0,
                                              leaky(c[i][j][1] + by) * s0);
                *(__half2*)(g_h1h + (size_t)r0 * HH + col) = v;
            }
            if (r1 < NN) {
                __half2 v = __floats2half2_rn(leaky(c[i][j][2] + bx) * s1,
                                              leaky(c[i][j][3] + by) * s1);
                *(__half2*)(g_h1h + (size_t)r1 * HH + col) = v;
            }
        }
    }
}

// GEMM2: h2[r,:] = leaky(agg2[r,:] @ W1 + b1);  g_m[:] += w(r) * h2[r,:]
__global__ __launch_bounds__(256, 1) void k_gemm2(
    const float* __restrict__ W1, const float* __restrict__ b1)
{
    __shared__ uint32_t As[128 * 32];
    __shared__ uint32_t Bs[32 * 256];
    const int t = threadIdx.x;
    const int lane = t & 31;
    const int warp = t >> 5;
    const int wr = warp >> 2;
    const int wc = warp & 3;
    const int r4 = lane >> 2;
    const int c4 = lane & 3;
    const int blockRow = blockIdx.x * 128;

    float c[4][8][4];
#pragma unroll
    for (int i = 0; i < 4; i++)
#pragma unroll
        for (int j = 0; j < 8; j++)
#pragma unroll
            for (int q = 0; q < 4; q++) c[i][j][q] = 0.f;

    const float4* ag4 = (const float4*)g_agg2;

    for (int kk = 0; kk < HH; kk += 32) {
        const float4* Bsrc = (const float4*)(W1 + (size_t)kk * HH);
        __syncthreads();
#pragma unroll
        for (int i = 0; i < 4; i++) {
            int idx = i * 256 + t;
            int row = idx >> 3;
            int q   = idx & 7;
            int gr  = blockRow + row;
            float4 av = make_float4(0.f, 0.f, 0.f, 0.f);
            if (gr < NN) av = ag4[(size_t)gr * 64 + (kk >> 2) + q];
            uint4 u = make_uint4(f2tf(av.x), f2tf(av.y), f2tf(av.z), f2tf(av.w));
            *(uint4*)&As[row * 32 + (q ^ (row & 7)) * 4] = u;
        }
#pragma unroll
        for (int i = 0; i < 8; i++) {
            int idx = i * 256 + t;
            int kr  = idx >> 6;
            int c44 = idx & 63;
            float4 bv = Bsrc[(size_t)kr * 64 + c44];
            uint4 u = make_uint4(f2tf(bv.x), f2tf(bv.y), f2tf(bv.z), f2tf(bv.w));
            *(uint4*)&Bs[kr * 256 + (c44 ^ ((kr & 3) << 1)) * 4] = u;
        }
        __syncthreads();
#pragma unroll
        for (int ks = 0; ks < 4; ks++) {
            uint32_t a[4][4], b[8][2];
#pragma unroll
            for (int i = 0; i < 4; i++) {
                int m  = wr * 64 + i * 16 + r4;
                int m7 = m & 7;
                int cA0 = (((ks * 2)     ^ m7) << 2) | c4;
                int cA1 = (((ks * 2 + 1) ^ m7) << 2) | c4;
                a[i][0] = As[m * 32 + cA0];
                a[i][1] = As[(m + 8) * 32 + cA0];
                a[i][2] = As[m * 32 + cA1];
                a[i][3] = As[(m + 8) * 32 + cA1];
            }
            int k0 = ks * 8 + c4;
#pragma unroll
            for (int j = 0; j < 8; j++) {
                int n = wc * 64 + j * 8 + r4;
                int colB = n ^ (c4 << 3);
                b[j][0] = Bs[k0 * 256 + colB];
                b[j][1] = Bs[(k0 + 4) * 256 + colB];
            }
#pragma unroll
            for (int i = 0; i < 4; i++)
#pragma unroll
                for (int j = 0; j < 8; j++)
                    mma_tf32(c[i][j], a[i][0], a[i][1], a[i][2], a[i][3], b[j][0], b[j][1]);
        }
    }

    // fused epilogue: weighted column sums into g_m (colacc reuses As)
    __syncthreads();
    float* colacc = (float*)As;
    colacc[t] = 0.f;
    __syncthreads();

    float w0v[4], w1v[4];
#pragma unroll
    for (int i = 0; i < 4; i++) {
        int r0 = blockRow + wr * 64 + i * 16 + r4;
        int r1 = r0 + 8;
        w0v[i] = (r0 < NN) ? g_wsum[r0] * rsqrtf((float)max(g_outdeg[r0], 1)) : 0.f;
        w1v[i] = (r1 < NN) ? g_wsum[r1] * rsqrtf((float)max(g_outdeg[r1], 1)) : 0.f;
    }
#pragma unroll
    for (int j = 0; j < 8; j++) {
        int col = wc * 64 + j * 8 + c4 * 2;
        float bx = b1[col], by = b1[col + 1];
        float accLo = 0.f, accHi = 0.f;
#pragma unroll
        for (int i = 0; i < 4; i++) {
            accLo += w0v[i] * leaky(c[i][j][0] + bx) + w1v[i] * leaky(c[i][j][2] + bx);
            accHi += w0v[i] * leaky(c[i][j][1] + by) + w1v[i] * leaky(c[i][j][3] + by);
        }
        atomicAdd(&colacc[col], accLo);
        atomicAdd(&colacc[col + 1], accHi);
    }
    __syncthreads();
    atomicAdd(&g_m[t], colacc[t]);
}

// -------- tiny head: out = (g_m/N) @ {Wo,Wd} + {bo,bd} --------
__global__ void k_head(const float* __restrict__ Wo, const float* __restrict__ bo,
                       const float* __restrict__ Wd, const float* __restrict__ bd,
                       float* __restrict__ out, int out_size)
{
    int j = threadIdx.x;
    if (j >= out_size) return;
    const float invN = 1.0f / (float)NN;
    if (j < 100) {
        float acc = 0.f;
        for (int k = 0; k < HH; k++) acc += g_m[k] * Wo[k * 100 + j];
        out[j] = acc * invN + bo[j];
    } else if (j < 108) {
        int jj = j - 100;
        float acc = 0.f;
        for (int k = 0; k < HH; k++) acc += g_m[k] * Wd[k * 8 + jj];
        out[j] = acc * invN + bd[jj];
    }
}

extern "C" void kernel_launch(void* const* d_in, const int* in_sizes, int n_in,
                              void* d_out, int out_size)
{
    const float* n_feat  = (const float*)d_in[0];
    const int*   src     = (const int*)  d_in[1];
    const int*   dst     = (const int*)  d_in[2];
    const float* W_self  = (const float*)d_in[3];
    const float* W_neigh = (const float*)d_in[4];
    const float* b_sage  = (const float*)d_in[5];
    const float* W1      = (const float*)d_in[6];
    const float* b1      = (const float*)d_in[7];
    const float* Wo      = (const float*)d_in[8];
    const float* bo      = (const float*)d_in[9];
    const float* Wd      = (const float*)d_in[10];
    const float* bd      = (const float*)d_in[11];
    float* out = (float*)d_out;

    k_zero_small<<<(NN + 255) / 256, 256>>>();
    k_deg<<<(NE + 255) / 256, 256>>>(src, dst);
    k_assign<<<(NN + 255) / 256, 256>>>();
    k_scatter<<<(NE + 255) / 256, 256>>>(src, dst);
    k_nf2h<<<(NN * DI / 2 + 255) / 256, 256>>>(n_feat);
    k_agg1<<<(NN * 32 + 255) / 256, 256>>>();
    k_gemm1<<<(NN + 127) / 128, 256>>>(n_feat, W_self, W_neigh, b_sage);
    k_agg2<<<(NN * 32 + 255) / 256, 256>>>();
    k_gemm2<<<(NN + 127) / 128, 256>>>(W1, b1);
    k_head<<<1, 128>>>(Wo, bo, Wd, bd, out, out_size);
}

// round 6
// speedup vs baseline: 2.8095x; 1.2146x over previous
#include <cuda_runtime.h>
#include <cuda_fp16.h>
#include <cstdint>

#define NN 50000
#define NE 800000
#define DI 128
#define HH 256

// -------- scratch (static device globals) --------
__device__ __half g_nfh [(size_t)NN * DI];  // fp16 copy of n_feat      (12.8 MB)
__device__ __half g_a1h [(size_t)NN * DI];  // mean-agg n_feat, fp16    (12.8 MB)
__device__ __half g_h1h [(size_t)NN * HH];  // h1 * outdeg^-1/2, fp16   (25.6 MB)
__device__ __half g_a2h [(size_t)NN * HH];  // indeg^-1/2 * sum h1, fp16(25.6 MB)
__device__ __half g_Wst [(size_t)HH * HH];  // [n][k] fp16 of [Wself;Wneigh]
__device__ __half g_W1t [(size_t)HH * HH];  // [n][k] fp16 of W1
__device__ int    g_indeg[NN];
__device__ int    g_outdeg[NN];
__device__ float  g_wsum[NN];
__device__ float  g_m[HH];
__device__ int    g_beg[NN];
__device__ int    g_cursor[NN];
__device__ int    g_csrc[NE];
__device__ int    g_total;

__device__ __forceinline__ float leaky(float x) {
    return (x >= 0.f) ? x : 0.01f * x;
}

__device__ __forceinline__ uint32_t s2u(const void* p) {
    return (uint32_t)__cvta_generic_to_shared(p);
}

#define LDSM4(r0, r1, r2, r3, addr)                                          \
    asm volatile("ldmatrix.sync.aligned.m8n8.x4.shared.b16 {%0,%1,%2,%3}, [%4];" \
                 : "=r"(r0), "=r"(r1), "=r"(r2), "=r"(r3) : "r"(addr))

__device__ __forceinline__ void mma_f16(float c[4],
    uint32_t a0, uint32_t a1, uint32_t a2, uint32_t a3,
    uint32_t b0, uint32_t b1)
{
    asm volatile(
        "mma.sync.aligned.m16n8k16.row.col.f32.f16.f16.f32 "
        "{%0,%1,%2,%3},{%4,%5,%6,%7},{%8,%9},{%0,%1,%2,%3};"
        : "+f"(c[0]), "+f"(c[1]), "+f"(c[2]), "+f"(c[3])
        : "r"(a0), "r"(a1), "r"(a2), "r"(a3), "r"(b0), "r"(b1));
}

// -------- zero the small per-launch state --------
__global__ void k_zero_small() {
    int i = blockIdx.x * blockDim.x + threadIdx.x;
    if (i < NN) { g_indeg[i] = 0; g_outdeg[i] = 0; g_wsum[i] = 0.f; }
    if (i < HH) g_m[i] = 0.f;
    if (i == 0) g_total = 0;
}

__global__ void k_deg(const int* __restrict__ src, const int* __restrict__ dst) {
    int e = blockIdx.x * blockDim.x + threadIdx.x;
    if (e < NE) {
        atomicAdd(&g_indeg[dst[e]], 1);
        atomicAdd(&g_outdeg[src[e]], 1);
    }
}

// -------- assign CSR row bases: warp-scan + one atomic per warp --------
__global__ __launch_bounds__(256) void k_assign() {
    int i = blockIdx.x * blockDim.x + threadIdx.x;
    int lane = threadIdx.x & 31;
    int d = (i < NN) ? g_indeg[i] : 0;
    int x = d;
#pragma unroll
    for (int off = 1; off < 32; off <<= 1) {
        int y = __shfl_up_sync(0xffffffffu, x, off);
        if (lane >= off) x += y;
    }
    int base = 0;
    if (lane == 31) base = atomicAdd(&g_total, x);
    base = __shfl_sync(0xffffffffu, base, 31);
    if (i < NN) {
        int b = base + x - d;
        g_beg[i] = b;
        g_cursor[i] = b;
    }
}

// -------- scatter edges into CSR (by dst) + accumulate wsum --------
__global__ void k_scatter(const int* __restrict__ src, const int* __restrict__ dst) {
    int e = blockIdx.x * blockDim.x + threadIdx.x;
    if (e >= NE) return;
    int s = src[e];
    int d = dst[e];
    int pos = atomicAdd(&g_cursor[d], 1);
    g_csrc[pos] = s;
    atomicAdd(&g_wsum[s], rsqrtf((float)g_indeg[d]));
}

// -------- n_feat -> fp16 copy --------
__global__ void k_nf2h(const float* __restrict__ nf) {
    int i = blockIdx.x * blockDim.x + threadIdx.x;
    if (i < NN * DI / 2) {
        float2 v = ((const float2*)nf)[i];
        ((__half2*)g_nfh)[i] = __floats2half2_rn(v.x, v.y);
    }
}

// -------- transpose+cvt weights into fp16 [n][k] --------
__global__ void k_wt(const float* __restrict__ Wself, const float* __restrict__ Wneigh,
                     const float* __restrict__ W1) {
    int idx = blockIdx.x * blockDim.x + threadIdx.x;
    if (idx < HH * HH) {              // g_Wst
        int n = idx >> 8, k = idx & 255;
        float v = (k < DI) ? Wself[k * HH + n] : Wneigh[(k - DI) * HH + n];
        g_Wst[idx] = __float2half_rn(v);
    } else if (idx < 2 * HH * HH) {   // g_W1t
        int j = idx - HH * HH;
        int n = j >> 8, k = j & 255;
        g_W1t[j] = __float2half_rn(W1[k * HH + n]);
    }
}

// -------- SAGE neighbor MEAN aggregation: warp/node, fp16 gather, fp16 out --------
__global__ __launch_bounds__(256) void k_agg1() {
    int w = (blockIdx.x * blockDim.x + threadIdx.x) >> 5;
    if (w >= NN) return;
    int lane = threadIdx.x & 31;
    int beg = g_beg[w];
    int deg = g_indeg[w];
    int end = beg + deg;
    const uint2* nh = (const uint2*)g_nfh;   // 4 halves per uint2; 32 per row
    float a0 = 0.f, a1 = 0.f, a2 = 0.f, a3 = 0.f;
    int i = beg;
    for (; i + 1 < end; i += 2) {
        int s0 = g_csrc[i];
        int s1 = g_csrc[i + 1];
        uint2 u = nh[(size_t)s0 * 32 + lane];
        uint2 v = nh[(size_t)s1 * 32 + lane];
        float2 f0 = __half22float2(*(__half2*)&u.x);
        float2 f1 = __half22float2(*(__half2*)&u.y);
        float2 g0 = __half22float2(*(__half2*)&v.x);
        float2 g1 = __half22float2(*(__half2*)&v.y);
        a0 += f0.x + g0.x; a1 += f0.y + g0.y;
        a2 += f1.x + g1.x; a3 += f1.y + g1.y;
    }
    if (i < end) {
        int s0 = g_csrc[i];
        uint2 u = nh[(size_t)s0 * 32 + lane];
        float2 f0 = __half22float2(*(__half2*)&u.x);
        float2 f1 = __half22float2(*(__half2*)&u.y);
        a0 += f0.x; a1 += f0.y; a2 += f1.x; a3 += f1.y;
    }
    float inv = (deg > 0) ? 1.f / (float)deg : 0.f;
    __half2 h0 = __floats2half2_rn(a0 * inv, a1 * inv);
    __half2 h1 = __floats2half2_rn(a2 * inv, a3 * inv);
    uint2 o;
    o.x = *(uint32_t*)&h0;
    o.y = *(uint32_t*)&h1;
    ((uint2*)g_a1h)[(size_t)w * 32 + lane] = o;
}

// -------- layer-2 aggregation: warp/node, fp16 gather, fp16 out (scaled indeg^-1/2) --------
__global__ __launch_bounds__(256) void k_agg2() {
    int w = (blockIdx.x * blockDim.x + threadIdx.x) >> 5;
    if (w >= NN) return;
    int lane = threadIdx.x & 31;
    int beg = g_beg[w];
    int deg = g_indeg[w];
    int end = beg + deg;
    const uint4* hh = (const uint4*)g_h1h;   // 8 halves per uint4; 32 per row
    float acc[8];
#pragma unroll
    for (int q = 0; q < 8; q++) acc[q] = 0.f;
    int i = beg;
    for (; i + 1 < end; i += 2) {
        int s0 = g_csrc[i];
        int s1 = g_csrc[i + 1];
        uint4 u = hh[(size_t)s0 * 32 + lane];
        uint4 v = hh[(size_t)s1 * 32 + lane];
        const uint32_t* up = &u.x;
        const uint32_t* vp = &v.x;
#pragma unroll
        for (int q = 0; q < 4; q++) {
            float2 fu = __half22float2(*(__half2*)&up[q]);
            float2 fv = __half22float2(*(__half2*)&vp[q]);
            acc[2 * q]     += fu.x + fv.x;
            acc[2 * q + 1] += fu.y + fv.y;
        }
    }
    if (i < end) {
        int s0 = g_csrc[i];
        uint4 u = hh[(size_t)s0 * 32 + lane];
        const uint32_t* up = &u.x;
#pragma unroll
        for (int q = 0; q < 4; q++) {
            float2 fu = __half22float2(*(__half2*)&up[q]);
            acc[2 * q]     += fu.x;
            acc[2 * q + 1] += fu.y;
        }
    }
    float sc = rsqrtf((float)max(deg, 1));
    uint4 o;
    uint32_t* op = &o.x;
#pragma unroll
    for (int q = 0; q < 4; q++) {
        __half2 h = __floats2half2_rn(acc[2 * q] * sc, acc[2 * q + 1] * sc);
        op[q] = *(uint32_t*)&h;
    }
    ((uint4*)g_a2h)[(size_t)w * 32 + lane] = o;
}

// ============ fp16 GEMM, 128x256 tile, BK=32, ldmatrix + XOR swizzle ============
// smem rows are 64B (32 halves); 16B segment c at byte (c ^ ((row>>1)&3))*16.
// 8 warps: wr=warp>>2 (M 64), wc=warp&3 (N 64); frags i:0..3 (m16), j:0..7 (n8).

// GEMM1: h1h[r,:] = fp16( leaky([nfh | a1h][r,:] @ Wst^T + b) * outdeg^-1/2 )
__global__ __launch_bounds__(256, 1) void k_gemm1(const float* __restrict__ bsage)
{
    __shared__ __align__(16) uint8_t AsB[128 * 64];
    __shared__ __align__(16) uint8_t BsB[256 * 64];
    const int t = threadIdx.x;
    const int lane = t & 31;
    const int warp = t >> 5;
    const int wr = warp >> 2;
    const int wc = warp & 3;
    const int r4 = lane >> 2;
    const int c4 = lane & 3;
    const int blockRow = blockIdx.x * 128;
    const uint32_t asb = s2u(AsB);
    const uint32_t bsb = s2u(BsB);

    float c[4][8][4];
#pragma unroll
    for (int i = 0; i < 4; i++)
#pragma unroll
        for (int j = 0; j < 8; j++)
#pragma unroll
            for (int q = 0; q < 4; q++) c[i][j][q] = 0.f;

    for (int kk = 0; kk < 2 * DI; kk += 32) {
        const __half* Asrc = (kk < DI) ? (g_nfh + kk) : (g_a1h + (kk - DI));
        const __half* Bsrc = g_Wst + kk;
        __syncthreads();
#pragma unroll
        for (int i = 0; i < 2; i++) {
            int idx = i * 256 + t;
            int row = idx >> 2;
            int cg  = idx & 3;
            int gr  = blockRow + row;
            uint4 v = make_uint4(0u, 0u, 0u, 0u);
            if (gr < NN) v = *(const uint4*)(Asrc + (size_t)gr * DI + cg * 8);
            *(uint4*)&AsB[row * 64 + ((cg ^ ((row >> 1) & 3)) << 4)] = v;
        }
#pragma unroll
        for (int i = 0; i < 4; i++) {
            int idx = i * 256 + t;
            int row = idx >> 2;     // n
            int cg  = idx & 3;
            uint4 v = *(const uint4*)(Bsrc + (size_t)row * HH + cg * 8);
            *(uint4*)&BsB[row * 64 + ((cg ^ ((row >> 1) & 3)) << 4)] = v;
        }
        __syncthreads();
#pragma unroll
        for (int ks = 0; ks < 2; ks++) {
            uint32_t a[4][4], b[8][2];
#pragma unroll
            for (int i = 0; i < 4; i++) {
                int rowA = wr * 64 + i * 16 + (lane & 15);
                int cA = ks * 2 + (lane >> 4);
                uint32_t addr = asb + rowA * 64 + ((cA ^ ((rowA >> 1) & 3)) << 4);
                LDSM4(a[i][0], a[i][1], a[i][2], a[i][3], addr);
            }
#pragma unroll
            for (int p = 0; p < 4; p++) {
                int rowB = wc * 64 + p * 16 + ((lane >> 4) << 3) + (lane & 7);
                int cB = ks * 2 + ((lane >> 3) & 1);
                uint32_t addr = bsb + rowB * 64 + ((cB ^ ((rowB >> 1) & 3)) << 4);
                LDSM4(b[2 * p][0], b[2 * p][1], b[2 * p + 1][0], b[2 * p + 1][1], addr);
            }
#pragma unroll
            for (int i = 0; i < 4; i++)
#pragma unroll
                for (int j = 0; j < 8; j++)
                    mma_f16(c[i][j], a[i][0], a[i][1], a[i][2], a[i][3], b[j][0], b[j][1]);
        }
    }

    // epilogue: bias + leaky + outdeg^-1/2, store fp16
#pragma unroll
    for (int i = 0; i < 4; i++) {
        int r0 = blockRow + wr * 64 + i * 16 + r4;
        int r1 = r0 + 8;
        float s0 = (r0 < NN) ? rsqrtf((float)max(g_outdeg[r0], 1)) : 0.f;
        float s1 = (r1 < NN) ? rsqrtf((float)max(g_outdeg[r1], 1)) : 0.f;
#pragma unroll
        for (int j = 0; j < 8; j++) {
            int col = wc * 64 + j * 8 + c4 * 2;
            float bx = bsage[col], by = bsage[col + 1];
            if (r0 < NN) {
                __half2 v = __floats2half2_rn(leaky(c[i][j][0] + bx) * s0,
                                              leaky(c[i][j][1] + by) * s0);
                *(__half2*)(g_h1h + (size_t)r0 * HH + col) = v;
            }
            if (r1 < NN) {
                __half2 v = __floats2half2_rn(leaky(c[i][j][2] + bx) * s1,
                                              leaky(c[i][j][3] + by) * s1);
                *(__half2*)(g_h1h + (size_t)r1 * HH + col) = v;
            }
        }
    }
}

// GEMM2: h2[r,:] = leaky(a2h[r,:] @ W1t^T + b1);  g_m[:] += w(r) * h2[r,:]
__global__ __launch_bounds__(256, 1) void k_gemm2(const float* __restrict__ b1)
{
    __shared__ __align__(16) uint8_t AsB[128 * 64];
    __shared__ __align__(16) uint8_t BsB[256 * 64];
    __shared__ float colacc[256];
    const int t = threadIdx.x;
    const int lane = t & 31;
    const int warp = t >> 5;
    const int wr = warp >> 2;
    const int wc = warp & 3;
    const int r4 = lane >> 2;
    const int c4 = lane & 3;
    const int blockRow = blockIdx.x * 128;
    const uint32_t asb = s2u(AsB);
    const uint32_t bsb = s2u(BsB);

    colacc[t] = 0.f;

    float c[4][8][4];
#pragma unroll
    for (int i = 0; i < 4; i++)
#pragma unroll
        for (int j = 0; j < 8; j++)
#pragma unroll
            for (int q = 0; q < 4; q++) c[i][j][q] = 0.f;

    for (int kk = 0; kk < HH; kk += 32) {
        const __half* Asrc = g_a2h + kk;
        const __half* Bsrc = g_W1t + kk;
        __syncthreads();
#pragma unroll
        for (int i = 0; i < 2; i++) {
            int idx = i * 256 + t;
            int row = idx >> 2;
            int cg  = idx & 3;
            int gr  = blockRow + row;
            uint4 v = make_uint4(0u, 0u, 0u, 0u);
            if (gr < NN) v = *(const uint4*)(Asrc + (size_t)gr * HH + cg * 8);
            *(uint4*)&AsB[row * 64 + ((cg ^ ((row >> 1) & 3)) << 4)] = v;
        }
#pragma unroll
        for (int i = 0; i < 4; i++) {
            int idx = i * 256 + t;
            int row = idx >> 2;
            int cg  = idx & 3;
            uint4 v = *(const uint4*)(Bsrc + (size_t)row * HH + cg * 8);
            *(uint4*)&BsB[row * 64 + ((cg ^ ((row >> 1) & 3)) << 4)] = v;
        }
        __syncthreads();
#pragma unroll
        for (int ks = 0; ks < 2; ks++) {
            uint32_t a[4][4], b[8][2];
#pragma unroll
            for (int i = 0; i < 4; i++) {
                int rowA = wr * 64 + i * 16 + (lane & 15);
                int cA = ks * 2 + (lane >> 4);
                uint32_t addr = asb + rowA * 64 + ((cA ^ ((rowA >> 1) & 3)) << 4);
                LDSM4(a[i][0], a[i][1], a[i][2], a[i][3], addr);
            }
#pragma unroll
            for (int p = 0; p < 4; p++) {
                int rowB = wc * 64 + p * 16 + ((lane >> 4) << 3) + (lane & 7);
                int cB = ks * 2 + ((lane >> 3) & 1);
                uint32_t addr = bsb + rowB * 64 + ((cB ^ ((rowB >> 1) & 3)) << 4);
                LDSM4(b[2 * p][0], b[2 * p][1], b[2 * p + 1][0], b[2 * p + 1][1], addr);
            }
#pragma unroll
            for (int i = 0; i < 4; i++)
#pragma unroll
                for (int j = 0; j < 8; j++)
                    mma_f16(c[i][j], a[i][0], a[i][1], a[i][2], a[i][3], b[j][0], b[j][1]);
        }
    }

    // fused epilogue: weighted column sums into g_m
    __syncthreads();
    float w0v[4], w1v[4];
#pragma unroll
    for (int i = 0; i < 4; i++) {
        int r0 = blockRow + wr * 64 + i * 16 + r4;
        int r1 = r0 + 8;
        w0v[i] = (r0 < NN) ? g_wsum[r0] * rsqrtf((float)max(g_outdeg[r0], 1)) : 0.f;
        w1v[i] = (r1 < NN) ? g_wsum[r1] * rsqrtf((float)max(g_outdeg[r1], 1)) : 0.f;
    }
#pragma unroll
    for (int j = 0; j < 8; j++) {
        int col = wc * 64 + j * 8 + c4 * 2;
        float bx = b1[col], by = b1[col + 1];
        float accLo = 0.f, accHi = 0.f;
#pragma unroll
        for (int i = 0; i < 4; i++) {
            accLo += w0v[i] * leaky(c[i][j][0] + bx) + w1v[i] * leaky(c[i][j][2] + bx);
            accHi += w0v[i] * leaky(c[i][j][1] + by) + w1v[i] * leaky(c[i][j][3] + by);
        }
        atomicAdd(&colacc[col], accLo);
        atomicAdd(&colacc[col + 1], accHi);
    }
    __syncthreads();
    atomicAdd(&g_m[t], colacc[t]);
}

// -------- tiny head: out = (g_m/N) @ {Wo,Wd} + {bo,bd} --------
__global__ void k_head(const float* __restrict__ Wo, const float* __restrict__ bo,
                       const float* __restrict__ Wd, const float* __restrict__ bd,
                       float* __restrict__ out, int out_size)
{
    int j = threadIdx.x;
    if (j >= out_size) return;
    const float invN = 1.0f / (float)NN;
    if (j < 100) {
        float acc = 0.f;
        for (int k = 0; k < HH; k++) acc += g_m[k] * Wo[k * 100 + j];
        out[j] = acc * invN + bo[j];
    } else if (j < 108) {
        int jj = j - 100;
        float acc = 0.f;
        for (int k = 0; k < HH; k++) acc += g_m[k] * Wd[k * 8 + jj];
        out[j] = acc * invN + bd[jj];
    }
}

extern "C" void kernel_launch(void* const* d_in, const int* in_sizes, int n_in,
                              void* d_out, int out_size)
{
    const float* n_feat  = (const float*)d_in[0];
    const int*   src     = (const int*)  d_in[1];
    const int*   dst     = (const int*)  d_in[2];
    const float* W_self  = (const float*)d_in[3];
    const float* W_neigh = (const float*)d_in[4];
    const float* b_sage  = (const float*)d_in[5];
    const float* W1      = (const float*)d_in[6];
    const float* b1      = (const float*)d_in[7];
    const float* Wo      = (const float*)d_in[8];
    const float* bo      = (const float*)d_in[9];
    const float* Wd      = (const float*)d_in[10];
    const float* bd      = (const float*)d_in[11];
    float* out = (float*)d_out;

    k_zero_small<<<(NN + 255) / 256, 256>>>();
    k_deg<<<(NE + 255) / 256, 256>>>(src, dst);
    k_assign<<<(NN + 255) / 256, 256>>>();
    k_scatter<<<(NE + 255) / 256, 256>>>(src, dst);
    k_nf2h<<<(NN * DI / 2 + 255) / 256, 256>>>(n_feat);
    k_wt<<<(2 * HH * HH + 255) / 256, 256>>>(W_self, W_neigh, W1);
    k_agg1<<<(NN * 32 + 255) / 256, 256>>>();
    k_gemm1<<<(NN + 127) / 128, 256>>>(b_sage);
    k_agg2<<<(NN * 32 + 255) / 256, 256>>>();
    k_gemm2<<<(NN + 127) / 128, 256>>>(b1);
    k_head<<<1, 128>>>(Wo, bo, Wd, bd, out, out_size);
}

// round 7
// speedup vs baseline: 3.1722x; 1.1291x over previous
#include <cuda_runtime.h>
#include <cuda_fp16.h>
#include <cstdint>

#define NN 50000
#define NE 800000
#define DI 128
#define HH 256

// -------- scratch (static device globals) --------
__device__ __half g_nfh [(size_t)NN * DI];  // fp16 copy of n_feat      (12.8 MB)
__device__ __half g_a1h [(size_t)NN * DI];  // mean-agg n_feat, fp16    (12.8 MB)
__device__ __half g_h1h [(size_t)NN * HH];  // h1 * outdeg^-1/2, fp16   (25.6 MB)
__device__ __half g_a2h [(size_t)NN * HH];  // indeg^-1/2 * sum h1, fp16(25.6 MB)
__device__ __half g_Wst [(size_t)HH * HH];  // [n][k] fp16 of [Wself;Wneigh]
__device__ __half g_W1t [(size_t)HH * HH];  // [n][k] fp16 of W1
__device__ int    g_indeg[NN];
__device__ int    g_outdeg[NN];
__device__ float  g_wsum[NN];
__device__ float  g_m[HH];
__device__ int    g_beg[NN];
__device__ int    g_cursor[NN];
__device__ int    g_csrc[NE];
__device__ int    g_total;

__device__ __forceinline__ float leaky(float x) {
    return (x >= 0.f) ? x : 0.01f * x;
}

__device__ __forceinline__ uint32_t s2u(const void* p) {
    return (uint32_t)__cvta_generic_to_shared(p);
}

#define LDSM4(r0, r1, r2, r3, addr)                                          \
    asm volatile("ldmatrix.sync.aligned.m8n8.x4.shared.b16 {%0,%1,%2,%3}, [%4];" \
                 : "=r"(r0), "=r"(r1), "=r"(r2), "=r"(r3) : "r"(addr))

__device__ __forceinline__ void mma_f16(float c[4],
    uint32_t a0, uint32_t a1, uint32_t a2, uint32_t a3,
    uint32_t b0, uint32_t b1)
{
    asm volatile(
        "mma.sync.aligned.m16n8k16.row.col.f32.f16.f16.f32 "
        "{%0,%1,%2,%3},{%4,%5,%6,%7},{%8,%9},{%0,%1,%2,%3};"
        : "+f"(c[0]), "+f"(c[1]), "+f"(c[2]), "+f"(c[3])
        : "r"(a0), "r"(a1), "r"(a2), "r"(a3), "r"(b0), "r"(b1));
}

__device__ __forceinline__ void cpa16(uint32_t saddr, const void* g, int src_bytes) {
    asm volatile("cp.async.cg.shared.global [%0], [%1], 16, %2;"
                 :: "r"(saddr), "l"(g), "r"(src_bytes));
}
#define CPA_COMMIT() asm volatile("cp.async.commit_group;")
#define CPA_WAIT(n)  asm volatile("cp.async.wait_group %0;" :: "n"(n))

// -------- fused setup: zero small state + n_feat->fp16 + weight transpose --------
__global__ __launch_bounds__(256) void k_setup(
    const float* __restrict__ nf, const float* __restrict__ Wself,
    const float* __restrict__ Wneigh, const float* __restrict__ W1)
{
    int i = blockIdx.x * blockDim.x + threadIdx.x;
    if (i < NN) { g_indeg[i] = 0; g_outdeg[i] = 0; g_wsum[i] = 0.f; }
    if (i < HH) g_m[i] = 0.f;
    if (i == 0) g_total = 0;
    if (i < NN * DI / 2) {
        float2 v = ((const float2*)nf)[i];
        ((__half2*)g_nfh)[i] = __floats2half2_rn(v.x, v.y);
    }
    if (i < HH * HH) {                 // g_Wst
        int n = i >> 8, k = i & 255;
        float v = (k < DI) ? Wself[k * HH + n] : Wneigh[(k - DI) * HH + n];
        g_Wst[i] = __float2half_rn(v);
        g_W1t[i] = __float2half_rn(W1[k * HH + n]);
    }
}

// -------- indeg only --------
__global__ void k_deg(const int* __restrict__ dst) {
    int e = blockIdx.x * blockDim.x + threadIdx.x;
    if (e < NE) atomicAdd(&g_indeg[dst[e]], 1);
}

// -------- assign CSR row bases: warp-scan + one atomic per warp --------
__global__ __launch_bounds__(256) void k_assign() {
    int i = blockIdx.x * blockDim.x + threadIdx.x;
    int lane = threadIdx.x & 31;
    int d = (i < NN) ? g_indeg[i] : 0;
    int x = d;
#pragma unroll
    for (int off = 1; off < 32; off <<= 1) {
        int y = __shfl_up_sync(0xffffffffu, x, off);
        if (lane >= off) x += y;
    }
    int base = 0;
    if (lane == 31) base = atomicAdd(&g_total, x);
    base = __shfl_sync(0xffffffffu, base, 31);
    if (i < NN) {
        int b = base + x - d;
        g_beg[i] = b;
        g_cursor[i] = b;
    }
}

// -------- scatter edges into CSR (by dst) + outdeg + wsum --------
__global__ void k_scatter(const int* __restrict__ src, const int* __restrict__ dst) {
    int e = blockIdx.x * blockDim.x + threadIdx.x;
    if (e >= NE) return;
    int s = src[e];
    int d = dst[e];
    int pos = atomicAdd(&g_cursor[d], 1);
    g_csrc[pos] = s;
    atomicAdd(&g_outdeg[s], 1);
    atomicAdd(&g_wsum[s], rsqrtf((float)g_indeg[d]));
}

// -------- SAGE neighbor MEAN aggregation: warp/node, fp16 gather, fp16 out --------
__global__ __launch_bounds__(256) void k_agg1() {
    int w = (blockIdx.x * blockDim.x + threadIdx.x) >> 5;
    if (w >= NN) return;
    int lane = threadIdx.x & 31;
    int beg = g_beg[w];
    int deg = g_indeg[w];
    int end = beg + deg;
    const uint2* nh = (const uint2*)g_nfh;
    float a0 = 0.f, a1 = 0.f, a2 = 0.f, a3 = 0.f;
    int i = beg;
    for (; i + 1 < end; i += 2) {
        int s0 = g_csrc[i];
        int s1 = g_csrc[i + 1];
        uint2 u = nh[(size_t)s0 * 32 + lane];
        uint2 v = nh[(size_t)s1 * 32 + lane];
        float2 f0 = __half22float2(*(__half2*)&u.x);
        float2 f1 = __half22float2(*(__half2*)&u.y);
        float2 g0 = __half22float2(*(__half2*)&v.x);
        float2 g1 = __half22float2(*(__half2*)&v.y);
        a0 += f0.x + g0.x; a1 += f0.y + g0.y;
        a2 += f1.x + g1.x; a3 += f1.y + g1.y;
    }
    if (i < end) {
        int s0 = g_csrc[i];
        uint2 u = nh[(size_t)s0 * 32 + lane];
        float2 f0 = __half22float2(*(__half2*)&u.x);
        float2 f1 = __half22float2(*(__half2*)&u.y);
        a0 += f0.x; a1 += f0.y; a2 += f1.x; a3 += f1.y;
    }
    float inv = (deg > 0) ? 1.f / (float)deg : 0.f;
    __half2 h0 = __floats2half2_rn(a0 * inv, a1 * inv);
    __half2 h1 = __floats2half2_rn(a2 * inv, a3 * inv);
    uint2 o;
    o.x = *(uint32_t*)&h0;
    o.y = *(uint32_t*)&h1;
    ((uint2*)g_a1h)[(size_t)w * 32 + lane] = o;
}

// -------- layer-2 aggregation: warp/node, fp16 gather, fp16 out (scaled indeg^-1/2) --------
__global__ __launch_bounds__(256) void k_agg2() {
    int w = (blockIdx.x * blockDim.x + threadIdx.x) >> 5;
    if (w >= NN) return;
    int lane = threadIdx.x & 31;
    int beg = g_beg[w];
    int deg = g_indeg[w];
    int end = beg + deg;
    const uint4* hh = (const uint4*)g_h1h;
    float acc[8];
#pragma unroll
    for (int q = 0; q < 8; q++) acc[q] = 0.f;
    int i = beg;
    for (; i + 1 < end; i += 2) {
        int s0 = g_csrc[i];
        int s1 = g_csrc[i + 1];
        uint4 u = hh[(size_t)s0 * 32 + lane];
        uint4 v = hh[(size_t)s1 * 32 + lane];
        const uint32_t* up = &u.x;
        const uint32_t* vp = &v.x;
#pragma unroll
        for (int q = 0; q < 4; q++) {
            float2 fu = __half22float2(*(__half2*)&up[q]);
            float2 fv = __half22float2(*(__half2*)&vp[q]);
            acc[2 * q]     += fu.x + fv.x;
            acc[2 * q + 1] += fu.y + fv.y;
        }
    }
    if (i < end) {
        int s0 = g_csrc[i];
        uint4 u = hh[(size_t)s0 * 32 + lane];
        const uint32_t* up = &u.x;
#pragma unroll
        for (int q = 0; q < 4; q++) {
            float2 fu = __half22float2(*(__half2*)&up[q]);
            acc[2 * q]     += fu.x;
            acc[2 * q + 1] += fu.y;
        }
    }
    float sc = rsqrtf((float)max(deg, 1));
    uint4 o;
    uint32_t* op = &o.x;
#pragma unroll
    for (int q = 0; q < 4; q++) {
        __half2 h = __floats2half2_rn(acc[2 * q] * sc, acc[2 * q + 1] * sc);
        op[q] = *(uint32_t*)&h;
    }
    ((uint4*)g_a2h)[(size_t)w * 32 + lane] = o;
}

// ============ fp16 GEMM, 128x256 tile, BK=32, cp.async double-buffered ============
// Stage layout: A stage s at AsB + s*8192 (128 rows x 64B), B stage s at BsB + s*16384
// (256 rows x 64B). 16B segment c of row at byte (c ^ ((row>>1)&3))*16.

#define A_STAGE 8192
#define B_STAGE 16384

__device__ __forceinline__ void gemm_load_stage(
    uint32_t asb, uint32_t bsb, int stage, int t, int blockRow,
    const __half* __restrict__ Asrc, int aStride, const __half* __restrict__ Bsrc)
{
    uint32_t abase = asb + stage * A_STAGE;
    uint32_t bbase = bsb + stage * B_STAGE;
#pragma unroll
    for (int i = 0; i < 2; i++) {
        int idx = i * 256 + t;
        int row = idx >> 2;
        int cg  = idx & 3;
        int gr  = blockRow + row;
        int ok  = (gr < NN);
        int grc = ok ? gr : (NN - 1);
        cpa16(abase + row * 64 + ((cg ^ ((row >> 1) & 3)) << 4),
              Asrc + (size_t)grc * aStride + cg * 8, ok ? 16 : 0);
    }
#pragma unroll
    for (int i = 0; i < 4; i++) {
        int idx = i * 256 + t;
        int row = idx >> 2;
        int cg  = idx & 3;
        cpa16(bbase + row * 64 + ((cg ^ ((row >> 1) & 3)) << 4),
              Bsrc + (size_t)row * HH + cg * 8, 16);
    }
}

__device__ __forceinline__ void gemm_compute_stage(
    uint32_t asb, uint32_t bsb, int stage, int lane, int wr, int wc,
    float c[4][8][4])
{
    uint32_t abase = asb + stage * A_STAGE;
    uint32_t bbase = bsb + stage * B_STAGE;
#pragma unroll
    for (int ks = 0; ks < 2; ks++) {
        uint32_t a[4][4], b[8][2];
#pragma unroll
        for (int i = 0; i < 4; i++) {
            int rowA = wr * 64 + i * 16 + (lane & 15);
            int cA = ks * 2 + (lane >> 4);
            uint32_t addr = abase + rowA * 64 + ((cA ^ ((rowA >> 1) & 3)) << 4);
            LDSM4(a[i][0], a[i][1], a[i][2], a[i][3], addr);
        }
#pragma unroll
        for (int p = 0; p < 4; p++) {
            int rowB = wc * 64 + p * 16 + ((lane >> 4) << 3) + (lane & 7);
            int cB = ks * 2 + ((lane >> 3) & 1);
            uint32_t addr = bbase + rowB * 64 + ((cB ^ ((rowB >> 1) & 3)) << 4);
            LDSM4(b[2 * p][0], b[2 * p][1], b[2 * p + 1][0], b[2 * p + 1][1], addr);
        }
#pragma unroll
        for (int i = 0; i < 4; i++)
#pragma unroll
            for (int j = 0; j < 8; j++)
                mma_f16(c[i][j], a[i][0], a[i][1], a[i][2], a[i][3], b[j][0], b[j][1]);
    }
}

// GEMM1: h1h[r,:] = fp16( leaky([nfh | a1h][r,:] @ Wst^T + b) * outdeg^-1/2 )
__global__ __launch_bounds__(256, 1) void k_gemm1(const float* __restrict__ bsage)
{
    __shared__ __align__(16) uint8_t AsB[2 * A_STAGE];
    __shared__ __align__(16) uint8_t BsB[2 * B_STAGE];
    const int t = threadIdx.x;
    const int lane = t & 31;
    const int warp = t >> 5;
    const int wr = warp >> 2;
    const int wc = warp & 3;
    const int r4 = lane >> 2;
    const int c4 = lane & 3;
    const int blockRow = blockIdx.x * 128;
    const uint32_t asb = s2u(AsB);
    const uint32_t bsb = s2u(BsB);

    float c[4][8][4];
#pragma unroll
    for (int i = 0; i < 4; i++)
#pragma unroll
        for (int j = 0; j < 8; j++)
#pragma unroll
            for (int q = 0; q < 4; q++) c[i][j][q] = 0.f;

    // tiles 0..3: A from g_nfh (stride DI); 4..7: from g_a1h
    gemm_load_stage(asb, bsb, 0, t, blockRow, g_nfh, DI, g_Wst);
    CPA_COMMIT();
    int cur = 0;
#pragma unroll
    for (int tile = 0; tile < 8; tile++) {
        if (tile + 1 < 8) {
            int nt = tile + 1;
            const __half* Asrc = (nt < 4) ? (g_nfh + nt * 32) : (g_a1h + (nt - 4) * 32);
            gemm_load_stage(asb, bsb, 1 - cur, t, blockRow, Asrc, DI, g_Wst + nt * 32);
            CPA_COMMIT();
            CPA_WAIT(1);
        } else {
            CPA_WAIT(0);
        }
        __syncthreads();
        gemm_compute_stage(asb, bsb, cur, lane, wr, wc, c);
        __syncthreads();
        cur ^= 1;
    }

    // epilogue: bias + leaky + outdeg^-1/2, store fp16
#pragma unroll
    for (int i = 0; i < 4; i++) {
        int r0 = blockRow + wr * 64 + i * 16 + r4;
        int r1 = r0 + 8;
        float s0 = (r0 < NN) ? rsqrtf((float)max(g_outdeg[r0], 1)) : 0.f;
        float s1 = (r1 < NN) ? rsqrtf((float)max(g_outdeg[r1], 1)) : 0.f;
#pragma unroll
        for (int j = 0; j < 8; j++) {
            int col = wc * 64 + j * 8 + c4 * 2;
            float bx = bsage[col], by = bsage[col + 1];
            if (r0 < NN) {
                __half2 v = __floats2half2_rn(leaky(c[i][j][0] + bx) * s0,
                                              leaky(c[i][j][1] + by) * s0);
                *(__half2*)(g_h1h + (size_t)r0 * HH + col) = v;
            }
            if (r1 < NN) {
                __half2 v = __floats2half2_rn(leaky(c[i][j][2] + bx) * s1,
                                              leaky(c[i][j][3] + by) * s1);
                *(__half2*)(g_h1h + (size_t)r1 * HH + col) = v;
            }
        }
    }
}

// GEMM2: h2[r,:] = leaky(a2h[r,:] @ W1t^T + b1);  g_m[:] += w(r) * h2[r,:]
__global__ __launch_bounds__(256, 1) void k_gemm2(const float* __restrict__ b1)
{
    __shared__ __align__(16) uint8_t AsB[2 * A_STAGE];
    __shared__ __align__(16) uint8_t BsB[2 * B_STAGE];
    const int t = threadIdx.x;
    const int lane = t & 31;
    const int warp = t >> 5;
    const int wr = warp >> 2;
    const int wc = warp & 3;
    const int r4 = lane >> 2;
    const int c4 = lane & 3;
    const int blockRow = blockIdx.x * 128;
    const uint32_t asb = s2u(AsB);
    const uint32_t bsb = s2u(BsB);

    float c[4][8][4];
#pragma unroll
    for (int i = 0; i < 4; i++)
#pragma unroll
        for (int j = 0; j < 8; j++)
#pragma unroll
            for (int q = 0; q < 4; q++) c[i][j][q] = 0.f;

    gemm_load_stage(asb, bsb, 0, t, blockRow, g_a2h, HH, g_W1t);
    CPA_COMMIT();
    int cur = 0;
#pragma unroll
    for (int tile = 0; tile < 8; tile++) {
        if (tile + 1 < 8) {
            int nt = tile + 1;
            gemm_load_stage(asb, bsb, 1 - cur, t, blockRow, g_a2h + nt * 32, HH,
                            g_W1t + nt * 32);
            CPA_COMMIT();
            CPA_WAIT(1);
        } else {
            CPA_WAIT(0);
        }
        __syncthreads();
        gemm_compute_stage(asb, bsb, cur, lane, wr, wc, c);
        __syncthreads();
        cur ^= 1;
    }

    // fused epilogue: weighted column sums into g_m (colacc overlays AsB)
    float* colacc = (float*)AsB;
    colacc[t] = 0.f;
    __syncthreads();

    float w0v[4], w1v[4];
#pragma unroll
    for (int i = 0; i < 4; i++) {
        int r0 = blockRow + wr * 64 + i * 16 + r4;
        int r1 = r0 + 8;
        w0v[i] = (r0 < NN) ? g_wsum[r0] * rsqrtf((float)max(g_outdeg[r0], 1)) : 0.f;
        w1v[i] = (r1 < NN) ? g_wsum[r1] * rsqrtf((float)max(g_outdeg[r1], 1)) : 0.f;
    }
#pragma unroll
    for (int j = 0; j < 8; j++) {
        int col = wc * 64 + j * 8 + c4 * 2;
        float bx = b1[col], by = b1[col + 1];
        float accLo = 0.f, accHi = 0.f;
#pragma unroll
        for (int i = 0; i < 4; i++) {
            accLo += w0v[i] * leaky(c[i][j][0] + bx) + w1v[i] * leaky(c[i][j][2] + bx);
            accHi += w0v[i] * leaky(c[i][j][1] + by) + w1v[i] * leaky(c[i][j][3] + by);
        }
        atomicAdd(&colacc[col], accLo);
        atomicAdd(&colacc[col + 1], accHi);
    }
    __syncthreads();
    atomicAdd(&g_m[t], colacc[t]);
}

// -------- tiny head: out = (g_m/N) @ {Wo,Wd} + {bo,bd} --------
__global__ void k_head(const float* __restrict__ Wo, const float* __restrict__ bo,
                       const float* __restrict__ Wd, const float* __restrict__ bd,
                       float* __restrict__ out, int out_size)
{
    int j = threadIdx.x;
    if (j >= out_size) return;
    const float invN = 1.0f / (float)NN;
    if (j < 100) {
        float acc = 0.f;
        for (int k = 0; k < HH; k++) acc += g_m[k] * Wo[k * 100 + j];
        out[j] = acc * invN + bo[j];
    } else if (j < 108) {
        int jj = j - 100;
        float acc = 0.f;
        for (int k = 0; k < HH; k++) acc += g_m[k] * Wd[k * 8 + jj];
        out[j] = acc * invN + bd[jj];
    }
}

extern "C" void kernel_launch(void* const* d_in, const int* in_sizes, int n_in,
                              void* d_out, int out_size)
{
    const float* n_feat  = (const float*)d_in[0];
    const int*   src     = (const int*)  d_in[1];
    const int*   dst     = (const int*)  d_in[2];
    const float* W_self  = (const float*)d_in[3];
    const float* W_neigh = (const float*)d_in[4];
    const float* b_sage  = (const float*)d_in[5];
    const float* W1      = (const float*)d_in[6];
    const float* b1      = (const float*)d_in[7];
    const float* Wo      = (const float*)d_in[8];
    const float* bo      = (const float*)d_in[9];
    const float* Wd      = (const float*)d_in[10];
    const float* bd      = (const float*)d_in[11];
    float* out = (float*)d_out;

    k_setup<<<(NN * DI / 2 + 255) / 256, 256>>>(n_feat, W_self, W_neigh, W1);
    k_deg<<<(NE + 255) / 256, 256>>>(dst);
    k_assign<<<(NN + 255) / 256, 256>>>();
    k_scatter<<<(NE + 255) / 256, 256>>>(src, dst);
    k_agg1<<<(NN * 32 + 255) / 256, 256>>>();
    k_gemm1<<<(NN + 127) / 128, 256>>>(b_sage);
    k_agg2<<<(NN * 32 + 255) / 256, 256>>>();
    k_gemm2<<<(NN + 127) / 128, 256>>>(b1);
    k_head<<<1, 128>>>(Wo, bo, Wd, bd, out, out_size);
}

// round 8
// speedup vs baseline: 3.2032x; 1.0098x over previous
#include <cuda_runtime.h>
#include <cuda_fp16.h>
#include <cstdint>

#define NN 50000
#define NE 800000
#define DI 128
#define HH 256

// -------- scratch (static device globals) --------
__device__ __half g_nfh [(size_t)NN * DI];  // fp16 copy of n_feat      (12.8 MB)
__device__ __half g_a1h [(size_t)NN * DI];  // mean-agg n_feat, fp16    (12.8 MB)
__device__ __half g_h1h [(size_t)NN * HH];  // h1 * outdeg^-1/2, fp16   (25.6 MB)
__device__ __half g_a2h [(size_t)NN * HH];  // indeg^-1/2 * sum h1, fp16(25.6 MB)
__device__ __half g_Wst [(size_t)HH * HH];  // [n][k] fp16 of [Wself;Wneigh]
__device__ __half g_W1t [(size_t)HH * HH];  // [n][k] fp16 of W1
__device__ int    g_indeg[NN];
__device__ int    g_outdeg[NN];
__device__ float  g_wsum[NN];
__device__ float  g_m[HH];
__device__ int    g_beg[NN];
__device__ int    g_cursor[NN];
__device__ int    g_csrc[NE];
__device__ int    g_total;

__device__ __forceinline__ float leaky(float x) {
    return (x >= 0.f) ? x : 0.01f * x;
}

__device__ __forceinline__ uint32_t s2u(const void* p) {
    return (uint32_t)__cvta_generic_to_shared(p);
}

#define LDSM4(r0, r1, r2, r3, addr)                                          \
    asm volatile("ldmatrix.sync.aligned.m8n8.x4.shared.b16 {%0,%1,%2,%3}, [%4];" \
                 : "=r"(r0), "=r"(r1), "=r"(r2), "=r"(r3) : "r"(addr))

__device__ __forceinline__ void mma_f16(float c[4],
    uint32_t a0, uint32_t a1, uint32_t a2, uint32_t a3,
    uint32_t b0, uint32_t b1)
{
    asm volatile(
        "mma.sync.aligned.m16n8k16.row.col.f32.f16.f16.f32 "
        "{%0,%1,%2,%3},{%4,%5,%6,%7},{%8,%9},{%0,%1,%2,%3};"
        : "+f"(c[0]), "+f"(c[1]), "+f"(c[2]), "+f"(c[3])
        : "r"(a0), "r"(a1), "r"(a2), "r"(a3), "r"(b0), "r"(b1));
}

__device__ __forceinline__ void cpa16(uint32_t saddr, const void* g, int src_bytes) {
    asm volatile("cp.async.cg.shared.global [%0], [%1], 16, %2;"
                 :: "r"(saddr), "l"(g), "r"(src_bytes));
}
#define CPA_COMMIT() asm volatile("cp.async.commit_group;")
#define CPA_WAIT(n)  asm volatile("cp.async.wait_group %0;" :: "n"(n))

// -------- fused setup: zero small state + n_feat->fp16 + weight transpose --------
__global__ __launch_bounds__(256) void k_setup(
    const float* __restrict__ nf, const float* __restrict__ Wself,
    const float* __restrict__ Wneigh, const float* __restrict__ W1)
{
    int i = blockIdx.x * blockDim.x + threadIdx.x;
    if (i < NN) { g_indeg[i] = 0; g_outdeg[i] = 0; g_wsum[i] = 0.f; }
    if (i < HH) g_m[i] = 0.f;
    if (i == 0) g_total = 0;
    if (i < NN * DI / 2) {
        float2 v = ((const float2*)nf)[i];
        ((__half2*)g_nfh)[i] = __floats2half2_rn(v.x, v.y);
    }
    if (i < HH * HH) {                 // g_Wst
        int n = i >> 8, k = i & 255;
        float v = (k < DI) ? Wself[k * HH + n] : Wneigh[(k - DI) * HH + n];
        g_Wst[i] = __float2half_rn(v);
        g_W1t[i] = __float2half_rn(W1[k * HH + n]);
    }
}

// -------- indeg only: 4 edges/thread via int4 --------
__global__ void k_deg(const int* __restrict__ dst) {
    int i = blockIdx.x * blockDim.x + threadIdx.x;
    if (i < NE / 4) {
        int4 d = ((const int4*)dst)[i];
        atomicAdd(&g_indeg[d.x], 1);
        atomicAdd(&g_indeg[d.y], 1);
        atomicAdd(&g_indeg[d.z], 1);
        atomicAdd(&g_indeg[d.w], 1);
    }
}

// -------- assign CSR row bases: warp-scan + one atomic per warp --------
__global__ __launch_bounds__(256) void k_assign() {
    int i = blockIdx.x * blockDim.x + threadIdx.x;
    int lane = threadIdx.x & 31;
    int d = (i < NN) ? g_indeg[i] : 0;
    int x = d;
#pragma unroll
    for (int off = 1; off < 32; off <<= 1) {
        int y = __shfl_up_sync(0xffffffffu, x, off);
        if (lane >= off) x += y;
    }
    int base = 0;
    if (lane == 31) base = atomicAdd(&g_total, x);
    base = __shfl_sync(0xffffffffu, base, 31);
    if (i < NN) {
        int b = base + x - d;
        g_beg[i] = b;
        g_cursor[i] = b;
    }
}

// -------- scatter 4 edges/thread: CSR fill + outdeg + wsum --------
__global__ void k_scatter(const int* __restrict__ src, const int* __restrict__ dst) {
    int i = blockIdx.x * blockDim.x + threadIdx.x;
    if (i >= NE / 4) return;
    int4 s4 = ((const int4*)src)[i];
    int4 d4 = ((const int4*)dst)[i];
    const int* sp = &s4.x;
    const int* dp = &d4.x;
#pragma unroll
    for (int q = 0; q < 4; q++) {
        int s = sp[q];
        int d = dp[q];
        int pos = atomicAdd(&g_cursor[d], 1);
        g_csrc[pos] = s;
        atomicAdd(&g_outdeg[s], 1);
        atomicAdd(&g_wsum[s], rsqrtf((float)g_indeg[d]));
    }
}

// -------- SAGE neighbor MEAN aggregation: warp/node, 4-edge unrolled gather --------
__global__ __launch_bounds__(256) void k_agg1() {
    int w = (blockIdx.x * blockDim.x + threadIdx.x) >> 5;
    if (w >= NN) return;
    int lane = threadIdx.x & 31;
    int beg = g_beg[w];
    int deg = g_indeg[w];
    int end = beg + deg;
    const uint2* nh = (const uint2*)g_nfh;
    float a0 = 0.f, a1 = 0.f, a2 = 0.f, a3 = 0.f;
    int i = beg;
    for (; i + 3 < end; i += 4) {
        int s0 = g_csrc[i];
        int s1 = g_csrc[i + 1];
        int s2 = g_csrc[i + 2];
        int s3 = g_csrc[i + 3];
        uint2 u0 = nh[(size_t)s0 * 32 + lane];
        uint2 u1 = nh[(size_t)s1 * 32 + lane];
        uint2 u2 = nh[(size_t)s2 * 32 + lane];
        uint2 u3 = nh[(size_t)s3 * 32 + lane];
        float2 f;
        f = __half22float2(*(__half2*)&u0.x); a0 += f.x; a1 += f.y;
        f = __half22float2(*(__half2*)&u0.y); a2 += f.x; a3 += f.y;
        f = __half22float2(*(__half2*)&u1.x); a0 += f.x; a1 += f.y;
        f = __half22float2(*(__half2*)&u1.y); a2 += f.x; a3 += f.y;
        f = __half22float2(*(__half2*)&u2.x); a0 += f.x; a1 += f.y;
        f = __half22float2(*(__half2*)&u2.y); a2 += f.x; a3 += f.y;
        f = __half22float2(*(__half2*)&u3.x); a0 += f.x; a1 += f.y;
        f = __half22float2(*(__half2*)&u3.y); a2 += f.x; a3 += f.y;
    }
    for (; i < end; i++) {
        int s0 = g_csrc[i];
        uint2 u = nh[(size_t)s0 * 32 + lane];
        float2 f;
        f = __half22float2(*(__half2*)&u.x); a0 += f.x; a1 += f.y;
        f = __half22float2(*(__half2*)&u.y); a2 += f.x; a3 += f.y;
    }
    float inv = (deg > 0) ? 1.f / (float)deg : 0.f;
    __half2 h0 = __floats2half2_rn(a0 * inv, a1 * inv);
    __half2 h1 = __floats2half2_rn(a2 * inv, a3 * inv);
    uint2 o;
    o.x = *(uint32_t*)&h0;
    o.y = *(uint32_t*)&h1;
    ((uint2*)g_a1h)[(size_t)w * 32 + lane] = o;
}

// -------- layer-2 aggregation: warp/node, 4-edge unrolled gather (2 x uint4 each) --------
__global__ __launch_bounds__(256) void k_agg2() {
    int w = (blockIdx.x * blockDim.x + threadIdx.x) >> 5;
    if (w >= NN) return;
    int lane = threadIdx.x & 31;
    int beg = g_beg[w];
    int deg = g_indeg[w];
    int end = beg + deg;
    const uint2* hh = (const uint2*)g_h1h;   // 4 halves per uint2; 64 per row
    float acc[8];
#pragma unroll
    for (int q = 0; q < 8; q++) acc[q] = 0.f;
    int i = beg;
    for (; i + 3 < end; i += 4) {
        int s0 = g_csrc[i];
        int s1 = g_csrc[i + 1];
        int s2 = g_csrc[i + 2];
        int s3 = g_csrc[i + 3];
        // 8 independent 8B gathers in flight (2 per source row: halves [lane*4..) and [128+lane*4..))
        uint2 u0a = hh[(size_t)s0 * 64 + lane];
        uint2 u0b = hh[(size_t)s0 * 64 + 32 + lane];
        uint2 u1a = hh[(size_t)s1 * 64 + lane];
        uint2 u1b = hh[(size_t)s1 * 64 + 32 + lane];
        uint2 u2a = hh[(size_t)s2 * 64 + lane];
        uint2 u2b = hh[(size_t)s2 * 64 + 32 + lane];
        uint2 u3a = hh[(size_t)s3 * 64 + lane];
        uint2 u3b = hh[(size_t)s3 * 64 + 32 + lane];
        float2 f;
        f = __half22float2(*(__half2*)&u0a.x); acc[0] += f.x; acc[1] += f.y;
        f = __half22float2(*(__half2*)&u0a.y); acc[2] += f.x; acc[3] += f.y;
        f = __half22float2(*(__half2*)&u0b.x); acc[4] += f.x; acc[5] += f.y;
        f = __half22float2(*(__half2*)&u0b.y); acc[6] += f.x; acc[7] += f.y;
        f = __half22float2(*(__half2*)&u1a.x); acc[0] += f.x; acc[1] += f.y;
        f = __half22float2(*(__half2*)&u1a.y); acc[2] += f.x; acc[3] += f.y;
        f = __half22float2(*(__half2*)&u1b.x); acc[4] += f.x; acc[5] += f.y;
        f = __half22float2(*(__half2*)&u1b.y); acc[6] += f.x; acc[7] += f.y;
        f = __half22float2(*(__half2*)&u2a.x); acc[0] += f.x; acc[1] += f.y;
        f = __half22float2(*(__half2*)&u2a.y); acc[2] += f.x; acc[3] += f.y;
        f = __half22float2(*(__half2*)&u2b.x); acc[4] += f.x; acc[5] += f.y;
        f = __half22float2(*(__half2*)&u2b.y); acc[6] += f.x; acc[7] += f.y;
        f = __half22float2(*(__half2*)&u3a.x); acc[0] += f.x; acc[1] += f.y;
        f = __half22float2(*(__half2*)&u3a.y); acc[2] += f.x; acc[3] += f.y;
        f = __half22float2(*(__half2*)&u3b.x); acc[4] += f.x; acc[5] += f.y;
        f = __half22float2(*(__half2*)&u3b.y); acc[6] += f.x; acc[7] += f.y;
    }
    for (; i < end; i++) {
        int s0 = g_csrc[i];
        uint2 ua = hh[(size_t)s0 * 64 + lane];
        uint2 ub = hh[(size_t)s0 * 64 + 32 + lane];
        float2 f;
        f = __half22float2(*(__half2*)&ua.x); acc[0] += f.x; acc[1] += f.y;
        f = __half22float2(*(__half2*)&ua.y); acc[2] += f.x; acc[3] += f.y;
        f = __half22float2(*(__half2*)&ub.x); acc[4] += f.x; acc[5] += f.y;
        f = __half22float2(*(__half2*)&ub.y); acc[6] += f.x; acc[7] += f.y;
    }
    float sc = rsqrtf((float)max(deg, 1));
    __half2 h0 = __floats2half2_rn(acc[0] * sc, acc[1] * sc);
    __half2 h1 = __floats2half2_rn(acc[2] * sc, acc[3] * sc);
    __half2 h2 = __floats2half2_rn(acc[4] * sc, acc[5] * sc);
    __half2 h3 = __floats2half2_rn(acc[6] * sc, acc[7] * sc);
    uint2 oa, ob;
    oa.x = *(uint32_t*)&h0; oa.y = *(uint32_t*)&h1;
    ob.x = *(uint32_t*)&h2; ob.y = *(uint32_t*)&h3;
    ((uint2*)g_a2h)[(size_t)w * 64 + lane]      = oa;
    ((uint2*)g_a2h)[(size_t)w * 64 + 32 + lane] = ob;
}

// ============ fp16 GEMM, 128x256 tile, BK=32, cp.async double-buffered ============
#define A_STAGE 8192
#define B_STAGE 16384

__device__ __forceinline__ void gemm_load_stage(
    uint32_t asb, uint32_t bsb, int stage, int t, int blockRow,
    const __half* __restrict__ Asrc, int aStride, const __half* __restrict__ Bsrc)
{
    uint32_t abase = asb + stage * A_STAGE;
    uint32_t bbase = bsb + stage * B_STAGE;
#pragma unroll
    for (int i = 0; i < 2; i++) {
        int idx = i * 256 + t;
        int row = idx >> 2;
        int cg  = idx & 3;
        int gr  = blockRow + row;
        int ok  = (gr < NN);
        int grc = ok ? gr : (NN - 1);
        cpa16(abase + row * 64 + ((cg ^ ((row >> 1) & 3)) << 4),
              Asrc + (size_t)grc * aStride + cg * 8, ok ? 16 : 0);
    }
#pragma unroll
    for (int i = 0; i < 4; i++) {
        int idx = i * 256 + t;
        int row = idx >> 2;
        int cg  = idx & 3;
        cpa16(bbase + row * 64 + ((cg ^ ((row >> 1) & 3)) << 4),
              Bsrc + (size_t)row * HH + cg * 8, 16);
    }
}

__device__ __forceinline__ void gemm_compute_stage(
    uint32_t asb, uint32_t bsb, int stage, int lane, int wr, int wc,
    float c[4][8][4])
{
    uint32_t abase = asb + stage * A_STAGE;
    uint32_t bbase = bsb + stage * B_STAGE;
#pragma unroll
    for (int ks = 0; ks < 2; ks++) {
        uint32_t a[4][4], b[8][2];
#pragma unroll
        for (int i = 0; i < 4; i++) {
            int rowA = wr * 64 + i * 16 + (lane & 15);
            int cA = ks * 2 + (lane >> 4);
            uint32_t addr = abase + rowA * 64 + ((cA ^ ((rowA >> 1) & 3)) << 4);
            LDSM4(a[i][0], a[i][1], a[i][2], a[i][3], addr);
        }
#pragma unroll
        for (int p = 0; p < 4; p++) {
            int rowB = wc * 64 + p * 16 + ((lane >> 4) << 3) + (lane & 7);
            int cB = ks * 2 + ((lane >> 3) & 1);
            uint32_t addr = bbase + rowB * 64 + ((cB ^ ((rowB >> 1) & 3)) << 4);
            LDSM4(b[2 * p][0], b[2 * p][1], b[2 * p + 1][0], b[2 * p + 1][1], addr);
        }
#pragma unroll
        for (int i = 0; i < 4; i++)
#pragma unroll
            for (int j = 0; j < 8; j++)
                mma_f16(c[i][j], a[i][0], a[i][1], a[i][2], a[i][3], b[j][0], b[j][1]);
    }
}

// GEMM1: h1h[r,:] = fp16( leaky([nfh | a1h][r,:] @ Wst^T + b) * outdeg^-1/2 )
__global__ __launch_bounds__(256, 1) void k_gemm1(const float* __restrict__ bsage)
{
    __shared__ __align__(16) uint8_t AsB[2 * A_STAGE];
    __shared__ __align__(16) uint8_t BsB[2 * B_STAGE];
    const int t = threadIdx.x;
    const int lane = t & 31;
    const int warp = t >> 5;
    const int wr = warp >> 2;
    const int wc = warp & 3;
    const int r4 = lane >> 2;
    const int c4 = lane & 3;
    const int blockRow = blockIdx.x * 128;
    const uint32_t asb = s2u(AsB);
    const uint32_t bsb = s2u(BsB);

    float c[4][8][4];
#pragma unroll
    for (int i = 0; i < 4; i++)
#pragma unroll
        for (int j = 0; j < 8; j++)
#pragma unroll
            for (int q = 0; q < 4; q++) c[i][j][q] = 0.f;

    gemm_load_stage(asb, bsb, 0, t, blockRow, g_nfh, DI, g_Wst);
    CPA_COMMIT();
    int cur = 0;
#pragma unroll
    for (int tile = 0; tile < 8; tile++) {
        if (tile + 1 < 8) {
            int nt = tile + 1;
            const __half* Asrc = (nt < 4) ? (g_nfh + nt * 32) : (g_a1h + (nt - 4) * 32);
            gemm_load_stage(asb, bsb, 1 - cur, t, blockRow, Asrc, DI, g_Wst + nt * 32);
            CPA_COMMIT();
            CPA_WAIT(1);
        } else {
            CPA_WAIT(0);
        }
        __syncthreads();
        gemm_compute_stage(asb, bsb, cur, lane, wr, wc, c);
        __syncthreads();
        cur ^= 1;
    }

#pragma unroll
    for (int i = 0; i < 4; i++) {
        int r0 = blockRow + wr * 64 + i * 16 + r4;
        int r1 = r0 + 8;
        float s0 = (r0 < NN) ? rsqrtf((float)max(g_outdeg[r0], 1)) : 0.f;
        float s1 = (r1 < NN) ? rsqrtf((float)max(g_outdeg[r1], 1)) : 0.f;
#pragma unroll
        for (int j = 0; j < 8; j++) {
            int col = wc * 64 + j * 8 + c4 * 2;
            float bx = bsage[col], by = bsage[col + 1];
            if (r0 < NN) {
                __half2 v = __floats2half2_rn(leaky(c[i][j][0] + bx) * s0,
                                              leaky(c[i][j][1] + by) * s0);
                *(__half2*)(g_h1h + (size_t)r0 * HH + col) = v;
            }
            if (r1 < NN) {
                __half2 v = __floats2half2_rn(leaky(c[i][j][2] + bx) * s1,
                                              leaky(c[i][j][3] + by) * s1);
                *(__half2*)(g_h1h + (size_t)r1 * HH + col) = v;
            }
        }
    }
}

// GEMM2: h2[r,:] = leaky(a2h[r,:] @ W1t^T + b1);  g_m[:] += w(r) * h2[r,:]
__global__ __launch_bounds__(256, 1) void k_gemm2(const float* __restrict__ b1)
{
    __shared__ __align__(16) uint8_t AsB[2 * A_STAGE];
    __shared__ __align__(16) uint8_t BsB[2 * B_STAGE];
    const int t = threadIdx.x;
    const int lane = t & 31;
    const int warp = t >> 5;
    const int wr = warp >> 2;
    const int wc = warp & 3;
    const int r4 = lane >> 2;
    const int c4 = lane & 3;
    const int blockRow = blockIdx.x * 128;
    const uint32_t asb = s2u(AsB);
    const uint32_t bsb = s2u(BsB);

    float c[4][8][4];
#pragma unroll
    for (int i = 0; i < 4; i++)
#pragma unroll
        for (int j = 0; j < 8; j++)
#pragma unroll
            for (int q = 0; q < 4; q++) c[i][j][q] = 0.f;

    gemm_load_stage(asb, bsb, 0, t, blockRow, g_a2h, HH, g_W1t);
    CPA_COMMIT();
    int cur = 0;
#pragma unroll
    for (int tile = 0; tile < 8; tile++) {
        if (tile + 1 < 8) {
            int nt = tile + 1;
            gemm_load_stage(asb, bsb, 1 - cur, t, blockRow, g_a2h + nt * 32, HH,
                            g_W1t + nt * 32);
            CPA_COMMIT();
            CPA_WAIT(1);
        } else {
            CPA_WAIT(0);
        }
        __syncthreads();
        gemm_compute_stage(asb, bsb, cur, lane, wr, wc, c);
        __syncthreads();
        cur ^= 1;
    }

    // fused epilogue: weighted column sums into g_m (colacc overlays AsB)
    float* colacc = (float*)AsB;
    colacc[t] = 0.f;
    __syncthreads();

    float w0v[4], w1v[4];
#pragma unroll
    for (int i = 0; i < 4; i++) {
        int r0 = blockRow + wr * 64 + i * 16 + r4;
        int r1 = r0 + 8;
        w0v[i] = (r0 < NN) ? g_wsum[r0] * rsqrtf((float)max(g_outdeg[r0], 1)) : 0.f;
        w1v[i] = (r1 < NN) ? g_wsum[r1] * rsqrtf((float)max(g_outdeg[r1], 1)) : 0.f;
    }
#pragma unroll
    for (int j = 0; j < 8; j++) {
        int col = wc * 64 + j * 8 + c4 * 2;
        float bx = b1[col], by = b1[col + 1];
        float accLo = 0.f, accHi = 0.f;
#pragma unroll
        for (int i = 0; i < 4; i++) {
            accLo += w0v[i] * leaky(c[i][j][0] + bx) + w1v[i] * leaky(c[i][j][2] + bx);
            accHi += w0v[i] * leaky(c[i][j][1] + by) + w1v[i] * leaky(c[i][j][3] + by);
        }
        atomicAdd(&colacc[col], accLo);
        atomicAdd(&colacc[col + 1], accHi);
    }
    __syncthreads();
    atomicAdd(&g_m[t], colacc[t]);
}

// -------- tiny head: out = (g_m/N) @ {Wo,Wd} + {bo,bd} --------
__global__ void k_head(const float* __restrict__ Wo, const float* __restrict__ bo,
                       const float* __restrict__ Wd, const float* __restrict__ bd,
                       float* __restrict__ out, int out_size)
{
    int j = threadIdx.x;
    if (j >= out_size) return;
    const float invN = 1.0f / (float)NN;
    if (j < 100) {
        float acc = 0.f;
        for (int k = 0; k < HH; k++) acc += g_m[k] * Wo[k * 100 + j];
        out[j] = acc * invN + bo[j];
    } else if (j < 108) {
        int jj = j - 100;
        float acc = 0.f;
        for (int k = 0; k < HH; k++) acc += g_m[k] * Wd[k * 8 + jj];
        out[j] = acc * invN + bd[jj];
    }
}

extern "C" void kernel_launch(void* const* d_in, const int* in_sizes, int n_in,
                              void* d_out, int out_size)
{
    const float* n_feat  = (const float*)d_in[0];
    const int*   src     = (const int*)  d_in[1];
    const int*   dst     = (const int*)  d_in[2];
    const float* W_self  = (const float*)d_in[3];
    const float* W_neigh = (const float*)d_in[4];
    const float* b_sage  = (const float*)d_in[5];
    const float* W1      = (const float*)d_in[6];
    const float* b1      = (const float*)d_in[7];
    const float* Wo      = (const float*)d_in[8];
    const float* bo      = (const float*)d_in[9];
    const float* Wd      = (const float*)d_in[10];
    const float* bd      = (const float*)d_in[11];
    float* out = (float*)d_out;

    k_setup<<<(NN * DI / 2 + 255) / 256, 256>>>(n_feat, W_self, W_neigh, W1);
    k_deg<<<(NE / 4 + 255) / 256, 256>>>(dst);
    k_assign<<<(NN + 255) / 256, 256>>>();
    k_scatter<<<(NE / 4 + 255) / 256, 256>>>(src, dst);
    k_agg1<<<(NN * 32 + 255) / 256, 256>>>();
    k_gemm1<<<(NN + 127) / 128, 256>>>(b_sage);
    k_agg2<<<(NN * 32 + 255) / 256, 256>>>();
    k_gemm2<<<(NN + 127) / 128, 256>>>(b1);
    k_head<<<1, 128>>>(Wo, bo, Wd, bd, out, out_size);
}

// round 9
// speedup vs baseline: 3.3987x; 1.0610x over previous
#include <cuda_runtime.h>
#include <cuda_fp16.h>
#include <cstdint>

#define NN 50000
#define NE 800000
#define DI 128
#define HH 256

// -------- scratch (static device globals) --------
__device__ __half g_nfh [(size_t)NN * DI];
__device__ __half g_a1h [(size_t)NN * DI];
__device__ __half g_h1h [(size_t)NN * HH];
__device__ __half g_a2h [(size_t)NN * HH];
__device__ __half g_Wst [(size_t)HH * HH];  // [n][k] fp16 of [Wself;Wneigh]
__device__ __half g_W1t [(size_t)HH * HH];  // [n][k] fp16 of W1
__device__ int    g_indeg[NN];
__device__ int    g_outdeg[NN];
__device__ float  g_wsum[NN];
__device__ float  g_m[HH];
__device__ int    g_beg[NN];
__device__ int    g_cursor[NN];
__device__ int    g_csrc[NE];
__device__ int    g_total;

__device__ __forceinline__ float leaky(float x) {
    return (x >= 0.f) ? x : 0.01f * x;
}

__device__ __forceinline__ uint32_t s2u(const void* p) {
    return (uint32_t)__cvta_generic_to_shared(p);
}

__device__ __forceinline__ void red_add_i(int* p, int v) {
    asm volatile("red.global.add.s32 [%0], %1;"
                 :: "l"(__cvta_generic_to_global(p)), "r"(v) : "memory");
}
__device__ __forceinline__ void red_add_f(float* p, float v) {
    asm volatile("red.global.add.f32 [%0], %1;"
                 :: "l"(__cvta_generic_to_global(p)), "f"(v) : "memory");
}

#define LDSM4(r0, r1, r2, r3, addr)                                          \
    asm volatile("ldmatrix.sync.aligned.m8n8.x4.shared.b16 {%0,%1,%2,%3}, [%4];" \
                 : "=r"(r0), "=r"(r1), "=r"(r2), "=r"(r3) : "r"(addr))

__device__ __forceinline__ void mma_f16(float c[4],
    uint32_t a0, uint32_t a1, uint32_t a2, uint32_t a3,
    uint32_t b0, uint32_t b1)
{
    asm volatile(
        "mma.sync.aligned.m16n8k16.row.col.f32.f16.f16.f32 "
        "{%0,%1,%2,%3},{%4,%5,%6,%7},{%8,%9},{%0,%1,%2,%3};"
        : "+f"(c[0]), "+f"(c[1]), "+f"(c[2]), "+f"(c[3])
        : "r"(a0), "r"(a1), "r"(a2), "r"(a3), "r"(b0), "r"(b1));
}

__device__ __forceinline__ void cpa16(uint32_t saddr, const void* g, int src_bytes) {
    asm volatile("cp.async.cg.shared.global [%0], [%1], 16, %2;"
                 :: "r"(saddr), "l"(g), "r"(src_bytes));
}
#define CPA_COMMIT() asm volatile("cp.async.commit_group;")
#define CPA_WAIT(n)  asm volatile("cp.async.wait_group %0;" :: "n"(n))

// -------- zero per-launch state --------
__global__ void k_zero() {
    int i = blockIdx.x * blockDim.x + threadIdx.x;
    if (i < NN) { g_indeg[i] = 0; g_outdeg[i] = 0; g_wsum[i] = 0.f; }
    if (i < HH) g_m[i] = 0.f;
    if (i == 0) g_total = 0;
}

// -------- fused pre-pass: indeg (red.global) + nf->fp16 + weight transpose --------
__global__ __launch_bounds__(256) void k_pre(
    const int* __restrict__ dst, const float* __restrict__ nf,
    const float* __restrict__ Wself, const float* __restrict__ Wneigh,
    const float* __restrict__ W1)
{
    int i = blockIdx.x * blockDim.x + threadIdx.x;
    if (i < NE) red_add_i(&g_indeg[dst[i]], 1);
    if (i < NN * DI / 2) {
        float2 v = ((const float2*)nf)[i];
        ((__half2*)g_nfh)[i] = __floats2half2_rn(v.x, v.y);
    }
    if (i < HH * HH) {
        int n = i >> 8, k = i & 255;
        float v = (k < DI) ? Wself[k * HH + n] : Wneigh[(k - DI) * HH + n];
        g_Wst[i] = __float2half_rn(v);
        g_W1t[i] = __float2half_rn(W1[k * HH + n]);
    }
}

// -------- assign CSR row bases: warp-scan + one atomic per warp --------
__global__ __launch_bounds__(256) void k_assign() {
    int i = blockIdx.x * blockDim.x + threadIdx.x;
    int lane = threadIdx.x & 31;
    int d = (i < NN) ? g_indeg[i] : 0;
    int x = d;
#pragma unroll
    for (int off = 1; off < 32; off <<= 1) {
        int y = __shfl_up_sync(0xffffffffu, x, off);
        if (lane >= off) x += y;
    }
    int base = 0;
    if (lane == 31) base = atomicAdd(&g_total, x);
    base = __shfl_sync(0xffffffffu, base, 31);
    if (i < NN) {
        int b = base + x - d;
        g_beg[i] = b;
        g_cursor[i] = b;
    }
}

// -------- scatter: CSR fill (atomic return) + outdeg/wsum via red.global --------
__global__ void k_scatter(const int* __restrict__ src, const int* __restrict__ dst) {
    int e = blockIdx.x * blockDim.x + threadIdx.x;
    if (e >= NE) return;
    int s = src[e];
    int d = dst[e];
    red_add_i(&g_outdeg[s], 1);
    red_add_f(&g_wsum[s], rsqrtf((float)g_indeg[d]));
    int pos = atomicAdd(&g_cursor[d], 1);
    g_csrc[pos] = s;
}

// -------- SAGE neighbor MEAN aggregation: warp/node, fp16 gather --------
__global__ __launch_bounds__(256) void k_agg1() {
    int w = (blockIdx.x * blockDim.x + threadIdx.x) >> 5;
    if (w >= NN) return;
    int lane = threadIdx.x & 31;
    int beg = g_beg[w];
    int deg = g_indeg[w];
    int end = beg + deg;
    const uint2* nh = (const uint2*)g_nfh;
    float a0 = 0.f, a1 = 0.f, a2 = 0.f, a3 = 0.f;
    int i = beg;
    for (; i + 1 < end; i += 2) {
        int s0 = g_csrc[i];
        int s1 = g_csrc[i + 1];
        uint2 u = nh[(size_t)s0 * 32 + lane];
        uint2 v = nh[(size_t)s1 * 32 + lane];
        float2 f0 = __half22float2(*(__half2*)&u.x);
        float2 f1 = __half22float2(*(__half2*)&u.y);
        float2 g0 = __half22float2(*(__half2*)&v.x);
        float2 g1 = __half22float2(*(__half2*)&v.y);
        a0 += f0.x + g0.x; a1 += f0.y + g0.y;
        a2 += f1.x + g1.x; a3 += f1.y + g1.y;
    }
    if (i < end) {
        int s0 = g_csrc[i];
        uint2 u = nh[(size_t)s0 * 32 + lane];
        float2 f0 = __half22float2(*(__half2*)&u.x);
        float2 f1 = __half22float2(*(__half2*)&u.y);
        a0 += f0.x; a1 += f0.y; a2 += f1.x; a3 += f1.y;
    }
    float inv = (deg > 0) ? 1.f / (float)deg : 0.f;
    __half2 h0 = __floats2half2_rn(a0 * inv, a1 * inv);
    __half2 h1 = __floats2half2_rn(a2 * inv, a3 * inv);
    uint2 o;
    o.x = *(uint32_t*)&h0;
    o.y = *(uint32_t*)&h1;
    ((uint2*)g_a1h)[(size_t)w * 32 + lane] = o;
}

// -------- layer-2 aggregation: warp/node, fp16 gather --------
__global__ __launch_bounds__(256) void k_agg2() {
    int w = (blockIdx.x * blockDim.x + threadIdx.x) >> 5;
    if (w >= NN) return;
    int lane = threadIdx.x & 31;
    int beg = g_beg[w];
    int deg = g_indeg[w];
    int end = beg + deg;
    const uint2* hh = (const uint2*)g_h1h;
    float acc[8];
#pragma unroll
    for (int q = 0; q < 8; q++) acc[q] = 0.f;
    int i = beg;
    for (; i + 1 < end; i += 2) {
        int s0 = g_csrc[i];
        int s1 = g_csrc[i + 1];
        uint2 u0a = hh[(size_t)s0 * 64 + lane];
        uint2 u0b = hh[(size_t)s0 * 64 + 32 + lane];
        uint2 u1a = hh[(size_t)s1 * 64 + lane];
        uint2 u1b = hh[(size_t)s1 * 64 + 32 + lane];
        float2 f;
        f = __half22float2(*(__half2*)&u0a.x); acc[0] += f.x; acc[1] += f.y;
        f = __half22float2(*(__half2*)&u0a.y); acc[2] += f.x; acc[3] += f.y;
        f = __half22float2(*(__half2*)&u0b.x); acc[4] += f.x; acc[5] += f.y;
        f = __half22float2(*(__half2*)&u0b.y); acc[6] += f.x; acc[7] += f.y;
        f = __half22float2(*(__half2*)&u1a.x); acc[0] += f.x; acc[1] += f.y;
        f = __half22float2(*(__half2*)&u1a.y); acc[2] += f.x; acc[3] += f.y;
        f = __half22float2(*(__half2*)&u1b.x); acc[4] += f.x; acc[5] += f.y;
        f = __half22float2(*(__half2*)&u1b.y); acc[6] += f.x; acc[7] += f.y;
    }
    if (i < end) {
        int s0 = g_csrc[i];
        uint2 ua = hh[(size_t)s0 * 64 + lane];
        uint2 ub = hh[(size_t)s0 * 64 + 32 + lane];
        float2 f;
        f = __half22float2(*(__half2*)&ua.x); acc[0] += f.x; acc[1] += f.y;
        f = __half22float2(*(__half2*)&ua.y); acc[2] += f.x; acc[3] += f.y;
        f = __half22float2(*(__half2*)&ub.x); acc[4] += f.x; acc[5] += f.y;
        f = __half22float2(*(__half2*)&ub.y); acc[6] += f.x; acc[7] += f.y;
    }
    float sc = rsqrtf((float)max(deg, 1));
    __half2 h0 = __floats2half2_rn(acc[0] * sc, acc[1] * sc);
    __half2 h1 = __floats2half2_rn(acc[2] * sc, acc[3] * sc);
    __half2 h2 = __floats2half2_rn(acc[4] * sc, acc[5] * sc);
    __half2 h3 = __floats2half2_rn(acc[6] * sc, acc[7] * sc);
    uint2 oa, ob;
    oa.x = *(uint32_t*)&h0; oa.y = *(uint32_t*)&h1;
    ob.x = *(uint32_t*)&h2; ob.y = *(uint32_t*)&h3;
    ((uint2*)g_a2h)[(size_t)w * 64 + lane]      = oa;
    ((uint2*)g_a2h)[(size_t)w * 64 + 32 + lane] = ob;
}

// ============ fp16 GEMM, 128x128 tile, BK=32, cp.async double-buffered ============
// grid.y selects N-half. 2 CTAs/SM. A stage 8KB, B stage 8KB (128 n-rows x 64B).
#define A_STAGE 8192
#define B_STAGE 8192

__device__ __forceinline__ void gemm_load_stage(
    uint32_t asb, uint32_t bsb, int stage, int t, int blockRow,
    const __half* __restrict__ Asrc, int aStride, const __half* __restrict__ Bsrc)
{
    uint32_t abase = asb + stage * A_STAGE;
    uint32_t bbase = bsb + stage * B_STAGE;
#pragma unroll
    for (int i = 0; i < 2; i++) {
        int idx = i * 256 + t;
        int row = idx >> 2;
        int cg  = idx & 3;
        int gr  = blockRow + row;
        int ok  = (gr < NN);
        int grc = ok ? gr : (NN - 1);
        cpa16(abase + row * 64 + ((cg ^ ((row >> 1) & 3)) << 4),
              Asrc + (size_t)grc * aStride + cg * 8, ok ? 16 : 0);
    }
#pragma unroll
    for (int i = 0; i < 2; i++) {
        int idx = i * 256 + t;
        int row = idx >> 2;      // n within 128
        int cg  = idx & 3;
        cpa16(bbase + row * 64 + ((cg ^ ((row >> 1) & 3)) << 4),
              Bsrc + (size_t)row * HH + cg * 8, 16);
    }
}

__device__ __forceinline__ void gemm_compute_stage(
    uint32_t asb, uint32_t bsb, int stage, int lane, int wr, int wc,
    float c[4][4][4])
{
    uint32_t abase = asb + stage * A_STAGE;
    uint32_t bbase = bsb + stage * B_STAGE;
#pragma unroll
    for (int ks = 0; ks < 2; ks++) {
        uint32_t a[4][4], b[4][2];
#pragma unroll
        for (int i = 0; i < 4; i++) {
            int rowA = wr * 64 + i * 16 + (lane & 15);
            int cA = ks * 2 + (lane >> 4);
            uint32_t addr = abase + rowA * 64 + ((cA ^ ((rowA >> 1) & 3)) << 4);
            LDSM4(a[i][0], a[i][1], a[i][2], a[i][3], addr);
        }
#pragma unroll
        for (int p = 0; p < 2; p++) {
            int rowB = wc * 32 + p * 16 + ((lane >> 4) << 3) + (lane & 7);
            int cB = ks * 2 + ((lane >> 3) & 1);
            uint32_t addr = bbase + rowB * 64 + ((cB ^ ((rowB >> 1) & 3)) << 4);
            LDSM4(b[2 * p][0], b[2 * p][1], b[2 * p + 1][0], b[2 * p + 1][1], addr);
        }
#pragma unroll
        for (int i = 0; i < 4; i++)
#pragma unroll
            for (int j = 0; j < 4; j++)
                mma_f16(c[i][j], a[i][0], a[i][1], a[i][2], a[i][3], b[j][0], b[j][1]);
    }
}

// GEMM1: h1h[r, nh*128:+128] = fp16( leaky([nfh|a1h][r,:] @ Wst^T + b) * outdeg^-1/2 )
__global__ __launch_bounds__(256, 2) void k_gemm1(const float* __restrict__ bsage)
{
    __shared__ __align__(16) uint8_t AsB[2 * A_STAGE];
    __shared__ __align__(16) uint8_t BsB[2 * B_STAGE];
    const int t = threadIdx.x;
    const int lane = t & 31;
    const int warp = t >> 5;
    const int wr = warp >> 2;
    const int wc = warp & 3;
    const int r4 = lane >> 2;
    const int c4 = lane & 3;
    const int blockRow = blockIdx.x * 128;
    const int n0 = blockIdx.y * 128;
    const __half* Wt = g_Wst + (size_t)n0 * HH;
    const uint32_t asb = s2u(AsB);
    const uint32_t bsb = s2u(BsB);

    float c[4][4][4];
#pragma unroll
    for (int i = 0; i < 4; i++)
#pragma unroll
        for (int j = 0; j < 4; j++)
#pragma unroll
            for (int q = 0; q < 4; q++) c[i][j][q] = 0.f;

    gemm_load_stage(asb, bsb, 0, t, blockRow, g_nfh, DI, Wt);
    CPA_COMMIT();
    int cur = 0;
#pragma unroll
    for (int tile = 0; tile < 8; tile++) {
        if (tile + 1 < 8) {
            int nt = tile + 1;
            const __half* Asrc = (nt < 4) ? (g_nfh + nt * 32) : (g_a1h + (nt - 4) * 32);
            gemm_load_stage(asb, bsb, 1 - cur, t, blockRow, Asrc, DI, Wt + nt * 32);
            CPA_COMMIT();
            CPA_WAIT(1);
        } else {
            CPA_WAIT(0);
        }
        __syncthreads();
        gemm_compute_stage(asb, bsb, cur, lane, wr, wc, c);
        __syncthreads();
        cur ^= 1;
    }

#pragma unroll
    for (int i = 0; i < 4; i++) {
        int r0 = blockRow + wr * 64 + i * 16 + r4;
        int r1 = r0 + 8;
        float s0 = (r0 < NN) ? rsqrtf((float)max(g_outdeg[r0], 1)) : 0.f;
        float s1 = (r1 < NN) ? rsqrtf((float)max(g_outdeg[r1], 1)) : 0.f;
#pragma unroll
        for (int j = 0; j < 4; j++) {
            int col = n0 + wc * 32 + j * 8 + c4 * 2;
            float bx = bsage[col], by = bsage[col + 1];
            if (r0 < NN) {
                __half2 v = __floats2half2_rn(leaky(c[i][j][0] + bx) * s0,
                                              leaky(c[i][j][1] + by) * s0);
                *(__half2*)(g_h1h + (size_t)r0 * HH + col) = v;
            }
            if (r1 < NN) {
                __half2 v = __floats2half2_rn(leaky(c[i][j][2] + bx) * s1,
                                              leaky(c[i][j][3] + by) * s1);
                *(__half2*)(g_h1h + (size_t)r1 * HH + col) = v;
            }
        }
    }
}

// GEMM2: h2[r,:] = leaky(a2h[r,:] @ W1t^T + b1);  g_m[:] += w(r) * h2[r,:]
__global__ __launch_bounds__(256, 2) void k_gemm2(const float* __restrict__ b1)
{
    __shared__ __align__(16) uint8_t AsB[2 * A_STAGE];
    __shared__ __align__(16) uint8_t BsB[2 * B_STAGE];
    const int t = threadIdx.x;
    const int lane = t & 31;
    const int warp = t >> 5;
    const int wr = warp >> 2;
    const int wc = warp & 3;
    const int r4 = lane >> 2;
    const int c4 = lane & 3;
    const int blockRow = blockIdx.x * 128;
    const int n0 = blockIdx.y * 128;
    const __half* Wt = g_W1t + (size_t)n0 * HH;
    const uint32_t asb = s2u(AsB);
    const uint32_t bsb = s2u(BsB);

    float c[4][4][4];
#pragma unroll
    for (int i = 0; i < 4; i++)
#pragma unroll
        for (int j = 0; j < 4; j++)
#pragma unroll
            for (int q = 0; q < 4; q++) c[i][j][q] = 0.f;

    gemm_load_stage(asb, bsb, 0, t, blockRow, g_a2h, HH, Wt);
    CPA_COMMIT();
    int cur = 0;
#pragma unroll
    for (int tile = 0; tile < 8; tile++) {
        if (tile + 1 < 8) {
            int nt = tile + 1;
            gemm_load_stage(asb, bsb, 1 - cur, t, blockRow, g_a2h + nt * 32, HH,
                            Wt + nt * 32);
            CPA_COMMIT();
            CPA_WAIT(1);
        } else {
            CPA_WAIT(0);
        }
        __syncthreads();
        gemm_compute_stage(asb, bsb, cur, lane, wr, wc, c);
        __syncthreads();
        cur ^= 1;
    }

    // fused epilogue: weighted column sums into g_m (colacc overlays AsB)
    float* colacc = (float*)AsB;
    if (t < 128) colacc[t] = 0.f;
    __syncthreads();

    float w0v[4], w1v[4];
#pragma unroll
    for (int i = 0; i < 4; i++) {
        int r0 = blockRow + wr * 64 + i * 16 + r4;
        int r1 = r0 + 8;
        w0v[i] = (r0 < NN) ? g_wsum[r0] * rsqrtf((float)max(g_outdeg[r0], 1)) : 0.f;
        w1v[i] = (r1 < NN) ? g_wsum[r1] * rsqrtf((float)max(g_outdeg[r1], 1)) : 0.f;
    }
#pragma unroll
    for (int j = 0; j < 4; j++) {
        int lc = wc * 32 + j * 8 + c4 * 2;   // col within 128
        float bx = b1[n0 + lc], by = b1[n0 + lc + 1];
        float accLo = 0.f, accHi = 0.f;
#pragma unroll
        for (int i = 0; i < 4; i++) {
            accLo += w0v[i] * leaky(c[i][j][0] + bx) + w1v[i] * leaky(c[i][j][2] + bx);
            accHi += w0v[i] * leaky(c[i][j][1] + by) + w1v[i] * leaky(c[i][j][3] + by);
        }
        atomicAdd(&colacc[lc], accLo);
        atomicAdd(&colacc[lc + 1], accHi);
    }
    __syncthreads();
    if (t < 128) red_add_f(&g_m[n0 + t], colacc[t]);
}

// -------- tiny head: out = (g_m/N) @ {Wo,Wd} + {bo,bd} --------
__global__ void k_head(const float* __restrict__ Wo, const float* __restrict__ bo,
                       const float* __restrict__ Wd, const float* __restrict__ bd,
                       float* __restrict__ out, int out_size)
{
    int j = threadIdx.x;
    if (j >= out_size) return;
    const float invN = 1.0f / (float)NN;
    if (j < 100) {
        float acc = 0.f;
        for (int k = 0; k < HH; k++) acc += g_m[k] * Wo[k * 100 + j];
        out[j] = acc * invN + bo[j];
    } else if (j < 108) {
        int jj = j - 100;
        float acc = 0.f;
        for (int k = 0; k < HH; k++) acc += g_m[k] * Wd[k * 8 + jj];
        out[j] = acc * invN + bd[jj];
    }
}

extern "C" void kernel_launch(void* const* d_in, const int* in_sizes, int n_in,
                              void* d_out, int out_size)
{
    const float* n_feat  = (const float*)d_in[0];
    const int*   src     = (const int*)  d_in[1];
    const int*   dst     = (const int*)  d_in[2];
    const float* W_self  = (const float*)d_in[3];
    const float* W_neigh = (const float*)d_in[4];
    const float* b_sage  = (const float*)d_in[5];
    const float* W1      = (const float*)d_in[6];
    const float* b1      = (const float*)d_in[7];
    const float* Wo      = (const float*)d_in[8];
    const float* bo      = (const float*)d_in[9];
    const float* Wd      = (const float*)d_in[10];
    const float* bd      = (const float*)d_in[11];
    float* out = (float*)d_out;

    dim3 ggrid((NN + 127) / 128, 2);

    k_zero<<<(NN + 255) / 256, 256>>>();
    k_pre<<<(NN * DI / 2 + 255) / 256, 256>>>(dst, n_feat, W_self, W_neigh, W1);
    k_assign<<<(NN + 255) / 256, 256>>>();
    k_scatter<<<(NE + 255) / 256, 256>>>(src, dst);
    k_agg1<<<(NN * 32 + 255) / 256, 256>>>();
    k_gemm1<<<ggrid, 256>>>(b_sage);
    k_agg2<<<(NN * 32 + 255) / 256, 256>>>();
    k_gemm2<<<ggrid, 256>>>(b1);
    k_head<<<1, 128>>>(Wo, bo, Wd, bd, out, out_size);
}